// round 15
// baseline (speedup 1.0000x reference)
#include <cuda_runtime.h>
#include <cuda_bf16.h>
#include <cuda_fp16.h>
#include <cstddef>

// ---------------------------------------------------------------------------
// Problem constants
// ---------------------------------------------------------------------------
#define BATCH   8
#define SEQ     4096
#define NT      (BATCH * SEQ)      // 32768 tokens
#define DSTATE  16
#define DCONV   4
#define CHUNK   128
#define NCH     (SEQ / CHUNK)      // 32 chunks
#define GSTAGES 3
#define CTOK    64                 // conv token tile
// main blocks: d=256, di=512, r=16, xdw=48
// cmb block:   d=257, di=514, r=17, xdw=49

// ---------------------------------------------------------------------------
// Scratch (device globals — allocation-free)
// ---------------------------------------------------------------------------
__device__ float g_h   [(size_t)NT * 256];
__device__ float g_hc  [(size_t)NT * 257];
__device__ float g_hn  [(size_t)NT * 257];                       // final LN f32
__device__ __align__(16) __nv_bfloat16 g_hn_bf[(size_t)NT * 288];
__device__ __align__(16) __nv_bfloat16 g_xz_bf[(size_t)NT * 1056];
__device__ __align__(16) __nv_bfloat16 g_x_bf [(size_t)NT * 544];
__device__ float g_xdbl[(size_t)NT * 49];
__device__ __align__(16) __nv_bfloat16 g_xdbl_bf[(size_t)NT * 32];
__device__ __align__(16) __half2 g_edb[(size_t)NT * 514];        // (e, db) packed
__device__ __align__(16) __nv_bfloat16 g_yg_bf[(size_t)NT * 544];
__device__ float g_res [(size_t)NT];
__device__ float g_pool[(size_t)BATCH * 257];
__device__ float g_P [(size_t)BATCH * NCH * 16 * 514];
__device__ float g_S [(size_t)BATCH * NCH * 16 * 514];
__device__ __align__(16) __nv_bfloat16 g_wbf[2400000];           // padded bf16 weights

// ---------------------------------------------------------------------------
// Weight conversion: f32 (N,K) row-major -> bf16 (Npad, Kpad) zero-padded
// ---------------------------------------------------------------------------
struct WDesc { const float* src; long long off; int N, K, Kpad, total; };
struct WTab  { WDesc w[20]; };

__global__ void wconv_kernel(WTab tab, __nv_bfloat16* __restrict__ dst) {
    WDesc d = tab.w[blockIdx.y];
    int idx = blockIdx.x * 256 + threadIdx.x;
    if (idx >= d.total) return;
    int n = idx / d.Kpad;
    int k = idx - n * d.Kpad;
    float v = (n < d.N && k < d.K) ? d.src[(size_t)n * d.K + k] : 0.f;
    dst[d.off + idx] = __float2bfloat16(v);
}

// ---------------------------------------------------------------------------
// Embedding + residual channel (float4 copy)
// ---------------------------------------------------------------------------
__global__ void embed_kernel(const int* __restrict__ x,
                             const float* __restrict__ emb,
                             float* __restrict__ h, float* __restrict__ res) {
    int t = blockIdx.x;
    int id = x[t];
    const float4* e = reinterpret_cast<const float4*>(emb + (size_t)id * 256);
    float4* hr = reinterpret_cast<float4*>(h + (size_t)t * 256);
    int i = threadIdx.x;          // 64 threads, one float4 each
    hr[i] = e[i];
    if (i == 0) res[t] = (float)id;
}

// ---------------------------------------------------------------------------
// LayerNorm (f32 out): one warp per row
// ---------------------------------------------------------------------------
__global__ void ln_kernel(const float* __restrict__ in, float* __restrict__ out,
                          const float* __restrict__ w, const float* __restrict__ b,
                          int dim, int ntok) {
    int row  = (blockIdx.x * blockDim.x + threadIdx.x) >> 5;
    int lane = threadIdx.x & 31;
    if (row >= ntok) return;
    const float* r = in + (size_t)row * dim;
    float v[9];
    int cnt = (dim + 31) >> 5;
    float s = 0.f;
    #pragma unroll
    for (int i = 0; i < 9; i++) {
        if (i >= cnt) break;
        int d = lane + i * 32;
        v[i] = (d < dim) ? r[d] : 0.f;
        s += v[i];
    }
    #pragma unroll
    for (int o = 16; o; o >>= 1) s += __shfl_xor_sync(0xffffffffu, s, o);
    float mu = s / (float)dim;
    float var = 0.f;
    #pragma unroll
    for (int i = 0; i < 9; i++) {
        if (i >= cnt) break;
        int d = lane + i * 32;
        float dv = (d < dim) ? v[i] - mu : 0.f;
        var += dv * dv;
    }
    #pragma unroll
    for (int o = 16; o; o >>= 1) var += __shfl_xor_sync(0xffffffffu, var, o);
    float rstd = rsqrtf(var / (float)dim + 1e-5f);
    float* orow = out + (size_t)row * dim;
    #pragma unroll
    for (int i = 0; i < 9; i++) {
        if (i >= cnt) break;
        int d = lane + i * 32;
        if (d < dim) orow[d] = (v[i] - mu) * rstd * w[d] + b[d];
    }
}

// LayerNorm (bf16 out, padded ld).
// EVEN dim: channel-pair packed; ODD dim: scalar path (alignment).
__global__ void ln_bf16_kernel(const float* __restrict__ in,
                               __nv_bfloat16* __restrict__ out,
                               const float* __restrict__ w, const float* __restrict__ b,
                               int dim, int ldo) {
    int row  = (blockIdx.x * blockDim.x + threadIdx.x) >> 5;
    int lane = threadIdx.x & 31;
    if (row >= NT) return;
    const float* r = in + (size_t)row * dim;
    __nv_bfloat16* orow = out + (size_t)row * ldo;

    if ((dim & 1) == 0) {
        int npair = dim >> 1;
        int cnt = (npair + 31) >> 5;      // <= 5 for dim <= 320
        float v0[5], v1[5];
        float s = 0.f;
        #pragma unroll
        for (int i = 0; i < 5; i++) {
            if (i >= cnt) break;
            int p = lane + i * 32;
            if (p < npair) {
                float2 t = *reinterpret_cast<const float2*>(r + 2 * p);
                v0[i] = t.x; v1[i] = t.y;
            } else { v0[i] = 0.f; v1[i] = 0.f; }
            s += v0[i] + v1[i];
        }
        #pragma unroll
        for (int o = 16; o; o >>= 1) s += __shfl_xor_sync(0xffffffffu, s, o);
        float mu = s / (float)dim;
        float var = 0.f;
        #pragma unroll
        for (int i = 0; i < 5; i++) {
            if (i >= cnt) break;
            int p = lane + i * 32;
            if (p < npair) {
                float d0 = v0[i] - mu, d1 = v1[i] - mu;
                var += d0 * d0 + d1 * d1;
            }
        }
        #pragma unroll
        for (int o = 16; o; o >>= 1) var += __shfl_xor_sync(0xffffffffu, var, o);
        float rstd = rsqrtf(var / (float)dim + 1e-5f);
        #pragma unroll
        for (int i = 0; i < 5; i++) {
            if (i >= cnt) break;
            int p = lane + i * 32;
            if (p < npair) {
                float2 ww = *reinterpret_cast<const float2*>(w + 2 * p);
                float2 bb = *reinterpret_cast<const float2*>(b + 2 * p);
                float o0 = (v0[i] - mu) * rstd * ww.x + bb.x;
                float o1 = (v1[i] - mu) * rstd * ww.y + bb.y;
                *reinterpret_cast<__nv_bfloat162*>(&orow[2 * p]) =
                    __floats2bfloat162_rn(o0, o1);
            }
        }
    } else {
        float v[9];
        int cnt = (dim + 31) >> 5;
        float s = 0.f;
        #pragma unroll
        for (int i = 0; i < 9; i++) {
            if (i >= cnt) break;
            int d = lane + i * 32;
            v[i] = (d < dim) ? r[d] : 0.f;
            s += v[i];
        }
        #pragma unroll
        for (int o = 16; o; o >>= 1) s += __shfl_xor_sync(0xffffffffu, s, o);
        float mu = s / (float)dim;
        float var = 0.f;
        #pragma unroll
        for (int i = 0; i < 9; i++) {
            if (i >= cnt) break;
            int d = lane + i * 32;
            float dv = (d < dim) ? v[i] - mu : 0.f;
            var += dv * dv;
        }
        #pragma unroll
        for (int o = 16; o; o >>= 1) var += __shfl_xor_sync(0xffffffffu, var, o);
        float rstd = rsqrtf(var / (float)dim + 1e-5f);
        #pragma unroll
        for (int i = 0; i < 9; i++) {
            if (i >= cnt) break;
            int d = lane + i * 32;
            if (d < dim) orow[d] = __float2bfloat16((v[i] - mu) * rstd * w[d] + b[d]);
        }
    }
}

// LayerNorm (dim 256) + concat residual channel -> f32 rows of dim 257
__global__ void ln_concat_kernel(const float* __restrict__ in, float* __restrict__ out,
                                 const float* __restrict__ w, const float* __restrict__ b,
                                 const float* __restrict__ res) {
    int row  = (blockIdx.x * blockDim.x + threadIdx.x) >> 5;
    int lane = threadIdx.x & 31;
    if (row >= NT) return;
    const float* r = in + (size_t)row * 256;
    float v[8];
    float s = 0.f;
    #pragma unroll
    for (int i = 0; i < 8; i++) { v[i] = r[lane + i * 32]; s += v[i]; }
    #pragma unroll
    for (int o = 16; o; o >>= 1) s += __shfl_xor_sync(0xffffffffu, s, o);
    float mu = s * (1.f / 256.f);
    float var = 0.f;
    #pragma unroll
    for (int i = 0; i < 8; i++) { float dv = v[i] - mu; var += dv * dv; }
    #pragma unroll
    for (int o = 16; o; o >>= 1) var += __shfl_xor_sync(0xffffffffu, var, o);
    float rstd = rsqrtf(var * (1.f / 256.f) + 1e-5f);
    float* orow = out + (size_t)row * 257;
    #pragma unroll
    for (int i = 0; i < 8; i++) {
        int d = lane + i * 32;
        orow[d] = (v[i] - mu) * rstd * w[d] + b[d];
    }
    if (lane == 0) orow[256] = res[row];
}

// ---------------------------------------------------------------------------
// bf16 cp.async GEMM (r14-proven): BM=128 BN=64 BK=32, 3-stage cp.async,
// ldmatrix.x4 fragment loads, packed epilogue stores, __launch_bounds__(256,4).
// MODE 0: C[M,N] f32 store
// MODE 1: C[M,N] f32 accumulate (float2 when N even)
// MODE 2: dt path: edb = half2(exp(-sp), sp*u), exp(-sp) via sigmoid identity
// MODE 3: C f32 store + bf16x2 copy of cols<side_r into side
// MODE 4: bf16x2 store into side (ld side_ld), no f32
// ---------------------------------------------------------------------------
__device__ __forceinline__ void mma_bf16(float* c, const unsigned* a, const unsigned* b) {
    asm volatile(
        "mma.sync.aligned.m16n8k16.row.col.f32.bf16.bf16.f32 "
        "{%0,%1,%2,%3}, {%4,%5,%6,%7}, {%8,%9}, {%0,%1,%2,%3};"
        : "+f"(c[0]), "+f"(c[1]), "+f"(c[2]), "+f"(c[3])
        : "r"(a[0]), "r"(a[1]), "r"(a[2]), "r"(a[3]), "r"(b[0]), "r"(b[1]));
}

__device__ __forceinline__ void cpasync16(void* smem, const void* gmem) {
    unsigned saddr = (unsigned)__cvta_generic_to_shared(smem);
    asm volatile("cp.async.cg.shared.global [%0], [%1], 16;\n" :: "r"(saddr), "l"(gmem));
}

__device__ __forceinline__ void ldsm_x4(unsigned& r0, unsigned& r1,
                                        unsigned& r2, unsigned& r3, unsigned addr) {
    asm volatile("ldmatrix.sync.aligned.m8n8.x4.shared.b16 {%0,%1,%2,%3}, [%4];"
                 : "=r"(r0), "=r"(r1), "=r"(r2), "=r"(r3) : "r"(addr));
}

#define SWZ(row, c) (((((c) >> 2) ^ (((row) >> 1) & 3)) << 2) + ((c) & 3))

template <int MODE>
__global__ __launch_bounds__(256, 4)
void gemm_bf16_async(const __nv_bfloat16* __restrict__ A,
                     const __nv_bfloat16* __restrict__ W,
                     float* __restrict__ C, int M, int N, int Kpad,
                     const float* __restrict__ bias,
                     __nv_bfloat16* __restrict__ side, int side_ld, int side_r,
                     const __nv_bfloat16* __restrict__ ubf, int u_ld,
                     __half2* __restrict__ edb) {
    __shared__ unsigned As[GSTAGES][128 * 16];
    __shared__ unsigned Bs[GSTAGES][64 * 16];

    int tid  = threadIdx.x;
    int lane = tid & 31;
    int warp = tid >> 5;
    int wm = warp & 3, wn = warp >> 2;
    int g = lane >> 2, tg = lane & 3;
    int bm = blockIdx.y * 128;
    int bn = blockIdx.x * 64;
    int ntile = Kpad >> 5;

    int tq = lane >> 3, rl = lane & 7;
    unsigned as_base = (unsigned)__cvta_generic_to_shared(&As[0][0]);
    unsigned bs_base = (unsigned)__cvta_generic_to_shared(&Bs[0][0]);
    int rowA[2];
    rowA[0] = wm * 32 + 0  + (tq & 1) * 8 + rl;
    rowA[1] = wm * 32 + 16 + (tq & 1) * 8 + rl;
    int chA = tq >> 1;
    int colB[2];
    colB[0] = wn * 32 + 0  + (tq >> 1) * 8 + rl;
    colB[1] = wn * 32 + 16 + (tq >> 1) * 8 + rl;
    int chB = tq & 1;

    float acc[2][4][4];
    #pragma unroll
    for (int mt = 0; mt < 2; mt++)
        #pragma unroll
        for (int nt = 0; nt < 4; nt++)
            #pragma unroll
            for (int i = 0; i < 4; i++) acc[mt][nt][i] = 0.f;

    auto issue = [&](int buf, int t) {
        int k0 = t << 5;
        #pragma unroll
        for (int i = 0; i < 2; i++) {
            int idx = i * 256 + tid;
            int row = idx >> 2, ch = idx & 3;
            cpasync16(&As[buf][row * 16 + ((ch ^ ((row >> 1) & 3)) << 2)],
                      A + (size_t)(bm + row) * Kpad + k0 + ch * 8);
        }
        {
            int row = tid >> 2, ch = tid & 3;
            cpasync16(&Bs[buf][row * 16 + ((ch ^ ((row >> 1) & 3)) << 2)],
                      W + (size_t)(bn + row) * Kpad + k0 + ch * 8);
        }
        asm volatile("cp.async.commit_group;\n");
    };

    #pragma unroll
    for (int t = 0; t < GSTAGES - 1; t++) {
        if (t < ntile) issue(t, t);
        else asm volatile("cp.async.commit_group;\n");
    }

    for (int t = 0; t < ntile; t++) {
        asm volatile("cp.async.wait_group 1;\n");
        __syncthreads();
        int tn = t + GSTAGES - 1;
        if (tn < ntile) issue(tn % GSTAGES, tn);
        else asm volatile("cp.async.commit_group;\n");

        int buf = t % GSTAGES;
        unsigned abuf = as_base + (unsigned)(buf * 128 * 16 * 4);
        unsigned bbuf = bs_base + (unsigned)(buf * 64 * 16 * 4);
        #pragma unroll
        for (int ks = 0; ks < 2; ks++) {
            unsigned afr[2][4], bfr[4][2];
            #pragma unroll
            for (int mt = 0; mt < 2; mt++) {
                int r = rowA[mt];
                int ch = ks * 2 + chA;
                unsigned off = (unsigned)(r * 16 + ((ch ^ ((r >> 1) & 3)) << 2)) * 4u;
                ldsm_x4(afr[mt][0], afr[mt][1], afr[mt][2], afr[mt][3], abuf + off);
            }
            #pragma unroll
            for (int p = 0; p < 2; p++) {
                int cc = colB[p];
                int ch = ks * 2 + chB;
                unsigned off = (unsigned)(cc * 16 + ((ch ^ ((cc >> 1) & 3)) << 2)) * 4u;
                ldsm_x4(bfr[2 * p][0], bfr[2 * p][1],
                        bfr[2 * p + 1][0], bfr[2 * p + 1][1], bbuf + off);
            }
            #pragma unroll
            for (int mt = 0; mt < 2; mt++)
                #pragma unroll
                for (int nt = 0; nt < 4; nt++)
                    mma_bf16(acc[mt][nt], afr[mt], bfr[nt]);
        }
    }

    // epilogue — packed column-pair stores
    #pragma unroll
    for (int mt = 0; mt < 2; mt++) {
        int row0 = bm + wm * 32 + mt * 16 + g;
        #pragma unroll
        for (int nt = 0; nt < 4; nt++) {
            int col = bn + wn * 32 + nt * 8 + tg * 2;   // always even
            float* c = acc[mt][nt];
            #pragma unroll
            for (int rr = 0; rr < 2; rr++) {
                int ro = row0 + rr * 8;
                float v0 = c[rr * 2 + 0];
                float v1 = c[rr * 2 + 1];
                if (MODE == 0) {
                    if (col < N)     C[(size_t)ro * N + col]     = v0;
                    if (col + 1 < N) C[(size_t)ro * N + col + 1] = v1;
                }
                if (MODE == 1) {
                    if ((N & 1) == 0) {
                        if (col < N) {
                            float2* p = reinterpret_cast<float2*>(&C[(size_t)ro * N + col]);
                            float2 o = *p;
                            o.x += v0; o.y += v1;
                            *p = o;
                        }
                    } else {
                        if (col < N)     { size_t ix = (size_t)ro * N + col;     C[ix] += v0; }
                        if (col + 1 < N) { size_t ix = (size_t)ro * N + col + 1; C[ix] += v1; }
                    }
                }
                if (MODE == 2) {
                    if (col < N) {   // N even; col even -> col+1 < N too
                        float x0 = v0 + bias[col];
                        float x1 = v1 + bias[col + 1];
                        float q0 = __expf(-fabsf(x0));
                        float q1 = __expf(-fabsf(x1));
                        float sp0 = fmaxf(x0, 0.f) + log1pf(q0);
                        float sp1 = fmaxf(x1, 0.f) + log1pf(q1);
                        // exp(-softplus(x)) == (x>=0 ? q : 1) / (1+q)  (exact)
                        float e0 = (x0 >= 0.f ? q0 : 1.f) / (1.f + q0);
                        float e1 = (x1 >= 0.f ? q1 : 1.f) / (1.f + q1);
                        __nv_bfloat162 uu = *reinterpret_cast<const __nv_bfloat162*>(
                            &ubf[(size_t)ro * u_ld + col]);
                        float u0 = __bfloat162float(uu.x);
                        float u1 = __bfloat162float(uu.y);
                        __half2 p0 = __floats2half2_rn(e0, sp0 * u0);
                        __half2 p1 = __floats2half2_rn(e1, sp1 * u1);
                        uint2 pk;
                        pk.x = *reinterpret_cast<unsigned*>(&p0);
                        pk.y = *reinterpret_cast<unsigned*>(&p1);
                        *reinterpret_cast<uint2*>(&edb[(size_t)ro * N + col]) = pk;
                    }
                }
                if (MODE == 3) {
                    if (col < N)     C[(size_t)ro * N + col]     = v0;
                    if (col + 1 < N) C[(size_t)ro * N + col + 1] = v1;
                    if (col < side_r) {
                        *reinterpret_cast<__nv_bfloat162*>(
                            &side[(size_t)ro * side_ld + col]) =
                            __floats2bfloat162_rn(v0, v1);
                    }
                }
                if (MODE == 4) {
                    if (col < N) {   // N even
                        *reinterpret_cast<__nv_bfloat162*>(
                            &side[(size_t)ro * side_ld + col]) =
                            __floats2bfloat162_rn(v0, v1);
                    }
                }
            }
        }
    }
}

// ---------------------------------------------------------------------------
// Depthwise causal conv1d (K=4) + SiLU — x half only (z handled in scan_pass3).
// Channel-PAIR: bf16x2 smem reads, bf16x2 x_bf store. No z read, no uz write.
// ---------------------------------------------------------------------------
__global__ void conv_fused_kernel(const __nv_bfloat16* __restrict__ xz, int ld_xz,
                                  const float* __restrict__ cw,
                                  const float* __restrict__ cb,
                                  __nv_bfloat16* __restrict__ x_bf, int ld_xbf,
                                  int di) {
    __shared__ __nv_bfloat16 sx[CTOK + 3][128];
    __shared__ float scw[4][128], scb[128];
    int tid = threadIdx.x;
    int c0 = blockIdx.x * 128;
    int t0 = blockIdx.y * CTOK;
    int l0 = t0 & (SEQ - 1);

    if (tid < 128) {
        int ch = c0 + tid;
        bool ok = ch < di;
        scb[tid] = ok ? cb[ch] : 0.f;
        #pragma unroll
        for (int k = 0; k < 4; k++) scw[k][tid] = ok ? cw[ch * 4 + k] : 0.f;
    }
    for (int idx = tid; idx < (CTOK + 3) * 128; idx += 256) {
        int row = idx >> 7, chl = idx & 127;
        int ch = c0 + chl;
        int token = t0 - 3 + row;
        __nv_bfloat16 v = __float2bfloat16(0.f);
        if (ch < di && (row >= 3 || l0 > 0))
            v = xz[(size_t)token * ld_xz + ch];
        sx[row][chl] = v;
    }
    __syncthreads();

    int cp  = tid & 63;          // channel pair index
    int th  = tid >> 6;          // token group 0..3
    int chl = cp * 2;
    int c   = c0 + chl;
    if (c >= di) return;         // di even -> c+1 < di whenever c < di
    float w0a = scw[0][chl],     w1a = scw[1][chl],     w2a = scw[2][chl],     w3a = scw[3][chl];
    float w0b = scw[0][chl + 1], w1b = scw[1][chl + 1], w2b = scw[2][chl + 1], w3b = scw[3][chl + 1];
    float bba = scb[chl], bbb = scb[chl + 1];

    for (int tt = 0; tt < CTOK / 4; tt++) {
        int tl = th * (CTOK / 4) + tt;
        size_t token = (size_t)t0 + tl;
        float2 x0 = __bfloat1622float2(*reinterpret_cast<const __nv_bfloat162*>(&sx[tl][chl]));
        float2 x1 = __bfloat1622float2(*reinterpret_cast<const __nv_bfloat162*>(&sx[tl + 1][chl]));
        float2 x2 = __bfloat1622float2(*reinterpret_cast<const __nv_bfloat162*>(&sx[tl + 2][chl]));
        float2 x3 = __bfloat1622float2(*reinterpret_cast<const __nv_bfloat162*>(&sx[tl + 3][chl]));
        float acc0 = bba + w0a * x0.x + w1a * x1.x + w2a * x2.x + w3a * x3.x;
        float acc1 = bbb + w0b * x0.y + w1b * x1.y + w2b * x2.y + w3b * x3.y;
        float u0 = acc0 / (1.f + __expf(-acc0));
        float u1 = acc1 / (1.f + __expf(-acc1));
        *reinterpret_cast<__nv_bfloat162*>(&x_bf[token * ld_xbf + c]) =
            __floats2bfloat162_rn(u0, u1);
    }
}

// ---------------------------------------------------------------------------
// Chunked parallel selective scan. Pass1/pass2 unchanged; pass3 now applies
// the gate inline: yg = (y + u*D) * silu(z), reading u (x_bf) and z (xz_bf)
// directly — the uz intermediate is gone.
// ---------------------------------------------------------------------------
__global__ void scan_pass1(const __half2* __restrict__ edb,
                           const float* __restrict__ xdbl, int ld_xd, int r,
                           const float* __restrict__ A_log,
                           float* __restrict__ P, float* __restrict__ S,
                           int di) {
    __shared__ float sB[CHUNK][17];
    __shared__ float sA[128][17];
    int tid = threadIdx.x;
    int c0 = blockIdx.x * 128, chunk = blockIdx.y, b = blockIdx.z;
    size_t tok0 = (size_t)b * SEQ + (size_t)chunk * CHUNK;
    for (int i = tid; i < CHUNK * 16; i += 128) {
        int tt = i >> 4, s = i & 15;
        sB[tt][s] = xdbl[(tok0 + tt) * ld_xd + r + s];
    }
    for (int i = tid; i < 128 * 16; i += 128) {
        int cc = i >> 4, s = i & 15;
        int ch = c0 + cc;
        sA[cc][s] = (ch < di) ? A_log[(size_t)ch * 16 + s] : 0.f;
    }
    __syncthreads();
    int c = c0 + tid;
    if (c >= di) return;

    bool fast = true;
    float a[16];
    #pragma unroll
    for (int s = 0; s < 16; s++) {
        a[s] = -__expf(sA[tid][s]);
        fast = fast && (fabsf(a[s] + (float)(s + 1)) <= 1e-5f * (float)(s + 1));
    }
    float st[16];
    #pragma unroll
    for (int s = 0; s < 16; s++) st[s] = 0.f;
    size_t obase = ((size_t)(b * NCH + chunk) * 16) * di + c;

    if (fast) {
        float prodE = 1.f;
        for (int t = 0; t < CHUNK; t++) {
            size_t tok = tok0 + t;
            float2 ed = __half22float2(edb[tok * di + c]);
            float e = ed.x, db = ed.y;
            prodE *= e;
            float ep = 1.f;
            #pragma unroll
            for (int s = 0; s < 16; s++) {
                ep *= e;
                st[s] = ep * st[s] + db * sB[t][s];
            }
        }
        float pp = 1.f;
        #pragma unroll
        for (int s = 0; s < 16; s++) {
            pp *= prodE;
            P[obase + (size_t)s * di] = pp;
            S[obase + (size_t)s * di] = st[s];
        }
    } else {
        float Pl[16];
        #pragma unroll
        for (int s = 0; s < 16; s++) Pl[s] = 1.f;
        for (int t = 0; t < CHUNK; t++) {
            size_t tok = tok0 + t;
            float2 ed = __half22float2(edb[tok * di + c]);
            float e = ed.x, db = ed.y;
            #pragma unroll
            for (int s = 0; s < 16; s++) {
                float dA = __powf(e, -a[s]);
                st[s] = dA * st[s] + db * sB[t][s];
                Pl[s] *= dA;
            }
        }
        #pragma unroll
        for (int s = 0; s < 16; s++) {
            P[obase + (size_t)s * di] = Pl[s];
            S[obase + (size_t)s * di] = st[s];
        }
    }
}

__global__ void scan_pass2(float* __restrict__ P, float* __restrict__ S, int di) {
    int per_b = 16 * di;
    int gi = blockIdx.x * blockDim.x + threadIdx.x;
    if (gi >= BATCH * per_b) return;
    int b = gi / per_b;
    int sc = gi - b * per_b;
    float st = 0.f;
    for (int ch = 0; ch < NCH; ch++) {
        size_t idx = (size_t)(b * NCH + ch) * per_b + sc;
        float p = P[idx];
        float sv = S[idx];
        S[idx] = st;                // init state entering chunk ch
        st = p * st + sv;
    }
}

__global__ void scan_pass3(const __half2* __restrict__ edb,
                           const float* __restrict__ xdbl, int ld_xd, int r,
                           const float* __restrict__ A_log,
                           const float* __restrict__ S,
                           const __nv_bfloat16* __restrict__ xz, int ld_xz,
                           const __nv_bfloat16* __restrict__ xbf, int ld_xbf,
                           const float* __restrict__ Dp,
                           __nv_bfloat16* __restrict__ yg, int ld_yg,
                           int di) {
    __shared__ float sBC[CHUNK][33];
    __shared__ float sA[128][17];
    __shared__ float sD[128];
    int tid = threadIdx.x;
    int c0 = blockIdx.x * 128, chunk = blockIdx.y, b = blockIdx.z;
    size_t tok0 = (size_t)b * SEQ + (size_t)chunk * CHUNK;
    for (int i = tid; i < CHUNK * 32; i += 128) {
        int tt = i >> 5, s = i & 31;
        sBC[tt][s] = xdbl[(tok0 + tt) * ld_xd + r + s];
    }
    for (int i = tid; i < 128 * 16; i += 128) {
        int cc = i >> 4, s = i & 15;
        int ch = c0 + cc;
        sA[cc][s] = (ch < di) ? A_log[(size_t)ch * 16 + s] : 0.f;
    }
    {
        int ch = c0 + tid;
        sD[tid] = (ch < di) ? Dp[ch] : 0.f;
    }
    __syncthreads();
    int c = c0 + tid;
    if (c >= di) return;

    bool fast = true;
    float a[16];
    #pragma unroll
    for (int s = 0; s < 16; s++) {
        a[s] = -__expf(sA[tid][s]);
        fast = fast && (fabsf(a[s] + (float)(s + 1)) <= 1e-5f * (float)(s + 1));
    }
    float Dc = sD[tid];
    float st[16];
    size_t sbase = ((size_t)(b * NCH + chunk) * 16) * di + c;
    #pragma unroll
    for (int s = 0; s < 16; s++) st[s] = S[sbase + (size_t)s * di];

    if (fast) {
        for (int t = 0; t < CHUNK; t++) {
            size_t tok = tok0 + t;
            float2 ed = __half22float2(edb[tok * di + c]);
            float e = ed.x, db = ed.y;
            float y = 0.f, ep = 1.f;
            #pragma unroll
            for (int s = 0; s < 16; s++) {
                ep *= e;
                st[s] = ep * st[s] + db * sBC[t][s];
                y += st[s] * sBC[t][16 + s];
            }
            float zf = __bfloat162float(xz[tok * ld_xz + di + c]);
            float zg = zf / (1.f + __expf(-zf));
            float uf = __bfloat162float(xbf[tok * ld_xbf + c]);
            yg[tok * ld_yg + c] = __float2bfloat16((y + uf * Dc) * zg);
        }
    } else {
        for (int t = 0; t < CHUNK; t++) {
            size_t tok = tok0 + t;
            float2 ed = __half22float2(edb[tok * di + c]);
            float e = ed.x, db = ed.y;
            float y = 0.f;
            #pragma unroll
            for (int s = 0; s < 16; s++) {
                float dA = __powf(e, -a[s]);
                st[s] = dA * st[s] + db * sBC[t][s];
                y += st[s] * sBC[t][16 + s];
            }
            float zf = __bfloat162float(xz[tok * ld_xz + di + c]);
            float zg = zf / (1.f + __expf(-zf));
            float uf = __bfloat162float(xbf[tok * ld_xbf + c]);
            yg[tok * ld_yg + c] = __float2bfloat16((y + uf * Dc) * zg);
        }
    }
}

// ---------------------------------------------------------------------------
// Mean pool + classifier
// ---------------------------------------------------------------------------
__global__ void pool_kernel(const float* __restrict__ hn, float* __restrict__ pool) {
    int b = blockIdx.x, dd = blockIdx.y;
    float s = 0.f;
    for (int l = threadIdx.x; l < SEQ; l += 128)
        s += hn[((size_t)b * SEQ + l) * 257 + dd];
    __shared__ float red[128];
    red[threadIdx.x] = s;
    __syncthreads();
    for (int o = 64; o; o >>= 1) {
        if (threadIdx.x < o) red[threadIdx.x] += red[threadIdx.x + o];
        __syncthreads();
    }
    if (threadIdx.x == 0) pool[b * 257 + dd] = red[0] * (1.f / (float)SEQ);
}

__global__ void cls_kernel(const float* __restrict__ pool,
                           const float* __restrict__ w,
                           const float* __restrict__ bias,
                           float* __restrict__ out) {
    int i = threadIdx.x;
    if (i >= BATCH * 16) return;
    int b = i >> 4, n = i & 15;
    float acc = bias[n];
    for (int dd = 0; dd < 257; dd++) acc += pool[b * 257 + dd] * w[n * 257 + dd];
    out[b * 16 + n] = acc;
}

// ---------------------------------------------------------------------------
// Host orchestration
// ---------------------------------------------------------------------------
static inline int align32(int x) { return (x + 31) & ~31; }

static inline void launch_gemm(const __nv_bfloat16* A, const __nv_bfloat16* W,
                               float* C, int M, int N, int Kpad, int mode,
                               const float* bias = nullptr,
                               __nv_bfloat16* side = nullptr, int side_ld = 0,
                               int side_r = 0,
                               const __nv_bfloat16* ubf = nullptr, int u_ld = 0,
                               __half2* edb = nullptr) {
    dim3 grid((N + 63) / 64, M / 128);
    switch (mode) {
    case 0: gemm_bf16_async<0><<<grid, 256>>>(A, W, C, M, N, Kpad, bias, side, side_ld, side_r, ubf, u_ld, edb); break;
    case 1: gemm_bf16_async<1><<<grid, 256>>>(A, W, C, M, N, Kpad, bias, side, side_ld, side_r, ubf, u_ld, edb); break;
    case 2: gemm_bf16_async<2><<<grid, 256>>>(A, W, C, M, N, Kpad, bias, side, side_ld, side_r, ubf, u_ld, edb); break;
    case 3: gemm_bf16_async<3><<<grid, 256>>>(A, W, C, M, N, Kpad, bias, side, side_ld, side_r, ubf, u_ld, edb); break;
    default: gemm_bf16_async<4><<<grid, 256>>>(A, W, C, M, N, Kpad, bias, side, side_ld, side_r, ubf, u_ld, edb); break;
    }
}

static void mamba_block(float* hbuf, int d, int di, int r,
                        const float* ln_w, const float* ln_b,
                        const float* conv_w, const float* conv_b,
                        const float* dt_b, const float* A_log, const float* Dp,
                        const __nv_bfloat16* w_in, const __nv_bfloat16* w_xp,
                        const __nv_bfloat16* w_dt, const __nv_bfloat16* w_out,
                        __nv_bfloat16* hn_bf, __nv_bfloat16* xz_bf,
                        __nv_bfloat16* x_bf, float* xdbl, __nv_bfloat16* xdbl_bf,
                        __half2* edb,
                        __nv_bfloat16* yg_bf, float* Pbuf, float* Sbuf) {
    int xdw = r + 2 * DSTATE;
    int dpad = align32(d), dipad = align32(di);

    ln_bf16_kernel<<<NT / 8, 256>>>(hbuf, hn_bf, ln_w, ln_b, d, dpad);
    // in-proj -> xz bf16 only
    launch_gemm(hn_bf, w_in, nullptr, NT, 2 * di, dpad, 4,
                nullptr, xz_bf, 1056, 0);
    // conv + silu (x half only)
    conv_fused_kernel<<<dim3((di + 127) / 128, NT / CTOK), 256>>>(
        xz_bf, 1056, conv_w, conv_b, x_bf, dipad, di);
    // x-proj -> xdbl f32 + bf16 side (dt_r part)
    launch_gemm(x_bf, w_xp, xdbl, NT, xdw, dipad, 3,
                nullptr, xdbl_bf, 32, r);
    // dt path: edb = half2(exp(-softplus), dt*u)
    launch_gemm(xdbl_bf, w_dt, nullptr, NT, di, 32, 2,
                dt_b, nullptr, 0, 0, x_bf, dipad, edb);
    // chunked parallel scan (pass3 applies gate inline from xz/x_bf/Dp)
    dim3 sg((di + 127) / 128, NCH, BATCH);
    scan_pass1<<<sg, 128>>>(edb, xdbl, xdw, r, A_log, Pbuf, Sbuf, di);
    scan_pass2<<<(BATCH * 16 * di + 255) / 256, 256>>>(Pbuf, Sbuf, di);
    scan_pass3<<<sg, 128>>>(edb, xdbl, xdw, r, A_log, Sbuf,
                            xz_bf, 1056, x_bf, dipad, Dp, yg_bf, dipad, di);
    // out-proj with fused residual add
    launch_gemm(yg_bf, w_out, hbuf, NT, d, dipad, 1);
}

extern "C" void kernel_launch(void* const* d_in, const int* in_sizes, int n_in,
                              void* d_out, int out_size) {
    const int*   x         = (const int*)  d_in[0];
    const float* emb       = (const float*)d_in[1];
    const float* blk_ln_w  = (const float*)d_in[2];
    const float* blk_ln_b  = (const float*)d_in[3];
    const float* blk_in_w  = (const float*)d_in[4];
    const float* blk_cv_w  = (const float*)d_in[5];
    const float* blk_cv_b  = (const float*)d_in[6];
    const float* blk_xp_w  = (const float*)d_in[7];
    const float* blk_dt_w  = (const float*)d_in[8];
    const float* blk_dt_b  = (const float*)d_in[9];
    const float* blk_A_log = (const float*)d_in[10];
    const float* blk_D     = (const float*)d_in[11];
    const float* blk_out_w = (const float*)d_in[12];
    const float* norm_w    = (const float*)d_in[13];
    const float* norm_b    = (const float*)d_in[14];
    const float* cmb_ln_w  = (const float*)d_in[15];
    const float* cmb_ln_b  = (const float*)d_in[16];
    const float* cmb_in_w  = (const float*)d_in[17];
    const float* cmb_cv_w  = (const float*)d_in[18];
    const float* cmb_cv_b  = (const float*)d_in[19];
    const float* cmb_xp_w  = (const float*)d_in[20];
    const float* cmb_dt_w  = (const float*)d_in[21];
    const float* cmb_dt_b  = (const float*)d_in[22];
    const float* cmb_A_log = (const float*)d_in[23];
    const float* cmb_D     = (const float*)d_in[24];
    const float* cmb_out_w = (const float*)d_in[25];
    const float* fin_w     = (const float*)d_in[26];
    const float* fin_b     = (const float*)d_in[27];
    const float* cls_w     = (const float*)d_in[28];
    const float* cls_b     = (const float*)d_in[29];
    float* out = (float*)d_out;

    float *p_h, *p_hc, *p_hn, *p_xdbl, *p_res, *p_pool, *p_P, *p_S;
    __nv_bfloat16 *p_hn_bf, *p_xz_bf, *p_x_bf, *p_xdbl_bf, *p_yg_bf, *p_wbf;
    __half2 *p_edb;
    cudaGetSymbolAddress((void**)&p_h,       g_h);
    cudaGetSymbolAddress((void**)&p_hc,      g_hc);
    cudaGetSymbolAddress((void**)&p_hn,      g_hn);
    cudaGetSymbolAddress((void**)&p_hn_bf,   g_hn_bf);
    cudaGetSymbolAddress((void**)&p_xz_bf,   g_xz_bf);
    cudaGetSymbolAddress((void**)&p_x_bf,    g_x_bf);
    cudaGetSymbolAddress((void**)&p_xdbl,    g_xdbl);
    cudaGetSymbolAddress((void**)&p_xdbl_bf, g_xdbl_bf);
    cudaGetSymbolAddress((void**)&p_edb,     g_edb);
    cudaGetSymbolAddress((void**)&p_yg_bf,   g_yg_bf);
    cudaGetSymbolAddress((void**)&p_res,     g_res);
    cudaGetSymbolAddress((void**)&p_pool,    g_pool);
    cudaGetSymbolAddress((void**)&p_P,       g_P);
    cudaGetSymbolAddress((void**)&p_S,       g_S);
    cudaGetSymbolAddress((void**)&p_wbf,     g_wbf);

    // -------- weight table (deterministic offsets) --------
    WTab tab;
    long long off = 0;
    int wi = 0;
    long long w_in_off[5], w_xp_off[5], w_dt_off[5], w_out_off[5];
    auto add = [&](const float* src, int N, int K) -> long long {
        int Kp = align32(K);
        int Np = (N + 63) & ~63;
        long long o = off;
        tab.w[wi].src = src; tab.w[wi].off = o;
        tab.w[wi].N = N; tab.w[wi].K = K; tab.w[wi].Kpad = Kp;
        tab.w[wi].total = Np * Kp;
        wi++;
        off += (long long)Np * Kp;
        return o;
    };
    for (int i = 0; i < 4; i++) {
        w_in_off[i]  = add(blk_in_w  + (size_t)i * 1024 * 256, 1024, 256);
        w_xp_off[i]  = add(blk_xp_w  + (size_t)i * 48 * 512,   48,  512);
        w_dt_off[i]  = add(blk_dt_w  + (size_t)i * 512 * 16,   512, 16);
        w_out_off[i] = add(blk_out_w + (size_t)i * 256 * 512,  256, 512);
    }
    w_in_off[4]  = add(cmb_in_w,  1028, 257);
    w_xp_off[4]  = add(cmb_xp_w,  49,  514);
    w_dt_off[4]  = add(cmb_dt_w,  514, 17);
    w_out_off[4] = add(cmb_out_w, 257, 514);

    wconv_kernel<<<dim3(1224, 20), 256>>>(tab, p_wbf);
    embed_kernel<<<NT, 64>>>(x, emb, p_h, p_res);

    for (int i = 0; i < 4; i++) {
        mamba_block(p_h, 256, 512, 16,
                    blk_ln_w + (size_t)i * 256, blk_ln_b + (size_t)i * 256,
                    blk_cv_w + (size_t)i * 512 * 4, blk_cv_b + (size_t)i * 512,
                    blk_dt_b + (size_t)i * 512,
                    blk_A_log + (size_t)i * 512 * 16, blk_D + (size_t)i * 512,
                    p_wbf + w_in_off[i], p_wbf + w_xp_off[i],
                    p_wbf + w_dt_off[i], p_wbf + w_out_off[i],
                    p_hn_bf, p_xz_bf, p_x_bf, p_xdbl, p_xdbl_bf,
                    p_edb, p_yg_bf, p_P, p_S);
    }

    ln_concat_kernel<<<NT / 8, 256>>>(p_h, p_hc, norm_w, norm_b, p_res);

    mamba_block(p_hc, 257, 514, 17,
                cmb_ln_w, cmb_ln_b, cmb_cv_w, cmb_cv_b, cmb_dt_b,
                cmb_A_log, cmb_D,
                p_wbf + w_in_off[4], p_wbf + w_xp_off[4],
                p_wbf + w_dt_off[4], p_wbf + w_out_off[4],
                p_hn_bf, p_xz_bf, p_x_bf, p_xdbl, p_xdbl_bf,
                p_edb, p_yg_bf, p_P, p_S);

    ln_kernel<<<NT / 8, 256>>>(p_hc, p_hn, fin_w, fin_b, 257, NT);
    pool_kernel<<<dim3(BATCH, 257), 128>>>(p_hn, p_pool);
    cls_kernel<<<1, 128>>>(p_pool, cls_w, cls_b, out);
}

// round 16
// speedup vs baseline: 1.1123x; 1.1123x over previous
#include <cuda_runtime.h>
#include <cuda_bf16.h>
#include <cuda_fp16.h>
#include <cstddef>

// ---------------------------------------------------------------------------
// Problem constants
// ---------------------------------------------------------------------------
#define BATCH   8
#define SEQ     4096
#define NT      (BATCH * SEQ)      // 32768 tokens
#define DSTATE  16
#define DCONV   4
#define CHUNK   128
#define NCH     (SEQ / CHUNK)      // 32 chunks
#define GSTAGES 3
#define CTOK    64                 // conv token tile
// main blocks: d=256, di=512, r=16, xdw=48
// cmb block:   d=257, di=514, r=17, xdw=49

// ---------------------------------------------------------------------------
// Scratch (device globals — allocation-free)
// ---------------------------------------------------------------------------
__device__ float g_h   [(size_t)NT * 256];
__device__ float g_hc  [(size_t)NT * 257];
__device__ float g_hn  [(size_t)NT * 257];                       // final LN f32
__device__ __align__(16) __nv_bfloat16 g_hn_bf[(size_t)NT * 288];
__device__ __align__(16) __nv_bfloat16 g_xz_bf[(size_t)NT * 1056];
__device__ __align__(16) __nv_bfloat16 g_x_bf [(size_t)NT * 544];
__device__ float g_xdbl[(size_t)NT * 49];
__device__ __align__(16) __nv_bfloat16 g_xdbl_bf[(size_t)NT * 32];
__device__ __align__(16) __half2 g_edb[(size_t)NT * 514];        // (e, db) packed
__device__ __align__(16) __half2 g_uz [(size_t)NT * 514];        // (zg, ug) packed
__device__ __align__(16) __nv_bfloat16 g_yg_bf[(size_t)NT * 544];
__device__ float g_res [(size_t)NT];
__device__ float g_pool[(size_t)BATCH * 257];
__device__ float g_P [(size_t)BATCH * NCH * 16 * 514];
__device__ float g_S [(size_t)BATCH * NCH * 16 * 514];
__device__ __align__(16) __nv_bfloat16 g_wbf[2400000];           // padded bf16 weights

// ---------------------------------------------------------------------------
// Weight conversion: f32 (N,K) row-major -> bf16 (Npad, Kpad) zero-padded
// ---------------------------------------------------------------------------
struct WDesc { const float* src; long long off; int N, K, Kpad, total; };
struct WTab  { WDesc w[20]; };

__global__ void wconv_kernel(WTab tab, __nv_bfloat16* __restrict__ dst) {
    WDesc d = tab.w[blockIdx.y];
    int idx = blockIdx.x * 256 + threadIdx.x;
    if (idx >= d.total) return;
    int n = idx / d.Kpad;
    int k = idx - n * d.Kpad;
    float v = (n < d.N && k < d.K) ? d.src[(size_t)n * d.K + k] : 0.f;
    dst[d.off + idx] = __float2bfloat16(v);
}

// ---------------------------------------------------------------------------
// Embedding + residual channel (float4 copy)
// ---------------------------------------------------------------------------
__global__ void embed_kernel(const int* __restrict__ x,
                             const float* __restrict__ emb,
                             float* __restrict__ h, float* __restrict__ res) {
    int t = blockIdx.x;
    int id = x[t];
    const float4* e = reinterpret_cast<const float4*>(emb + (size_t)id * 256);
    float4* hr = reinterpret_cast<float4*>(h + (size_t)t * 256);
    int i = threadIdx.x;          // 64 threads, one float4 each
    hr[i] = e[i];
    if (i == 0) res[t] = (float)id;
}

// ---------------------------------------------------------------------------
// LayerNorm (f32 out): one warp per row
// ---------------------------------------------------------------------------
__global__ void ln_kernel(const float* __restrict__ in, float* __restrict__ out,
                          const float* __restrict__ w, const float* __restrict__ b,
                          int dim, int ntok) {
    int row  = (blockIdx.x * blockDim.x + threadIdx.x) >> 5;
    int lane = threadIdx.x & 31;
    if (row >= ntok) return;
    const float* r = in + (size_t)row * dim;
    float v[9];
    int cnt = (dim + 31) >> 5;
    float s = 0.f;
    #pragma unroll
    for (int i = 0; i < 9; i++) {
        if (i >= cnt) break;
        int d = lane + i * 32;
        v[i] = (d < dim) ? r[d] : 0.f;
        s += v[i];
    }
    #pragma unroll
    for (int o = 16; o; o >>= 1) s += __shfl_xor_sync(0xffffffffu, s, o);
    float mu = s / (float)dim;
    float var = 0.f;
    #pragma unroll
    for (int i = 0; i < 9; i++) {
        if (i >= cnt) break;
        int d = lane + i * 32;
        float dv = (d < dim) ? v[i] - mu : 0.f;
        var += dv * dv;
    }
    #pragma unroll
    for (int o = 16; o; o >>= 1) var += __shfl_xor_sync(0xffffffffu, var, o);
    float rstd = rsqrtf(var / (float)dim + 1e-5f);
    float* orow = out + (size_t)row * dim;
    #pragma unroll
    for (int i = 0; i < 9; i++) {
        if (i >= cnt) break;
        int d = lane + i * 32;
        if (d < dim) orow[d] = (v[i] - mu) * rstd * w[d] + b[d];
    }
}

// LayerNorm (bf16 out, padded ld).
// EVEN dim: channel-pair packed; ODD dim: scalar path (alignment).
__global__ void ln_bf16_kernel(const float* __restrict__ in,
                               __nv_bfloat16* __restrict__ out,
                               const float* __restrict__ w, const float* __restrict__ b,
                               int dim, int ldo) {
    int row  = (blockIdx.x * blockDim.x + threadIdx.x) >> 5;
    int lane = threadIdx.x & 31;
    if (row >= NT) return;
    const float* r = in + (size_t)row * dim;
    __nv_bfloat16* orow = out + (size_t)row * ldo;

    if ((dim & 1) == 0) {
        int npair = dim >> 1;
        int cnt = (npair + 31) >> 5;      // <= 5 for dim <= 320
        float v0[5], v1[5];
        float s = 0.f;
        #pragma unroll
        for (int i = 0; i < 5; i++) {
            if (i >= cnt) break;
            int p = lane + i * 32;
            if (p < npair) {
                float2 t = *reinterpret_cast<const float2*>(r + 2 * p);
                v0[i] = t.x; v1[i] = t.y;
            } else { v0[i] = 0.f; v1[i] = 0.f; }
            s += v0[i] + v1[i];
        }
        #pragma unroll
        for (int o = 16; o; o >>= 1) s += __shfl_xor_sync(0xffffffffu, s, o);
        float mu = s / (float)dim;
        float var = 0.f;
        #pragma unroll
        for (int i = 0; i < 5; i++) {
            if (i >= cnt) break;
            int p = lane + i * 32;
            if (p < npair) {
                float d0 = v0[i] - mu, d1 = v1[i] - mu;
                var += d0 * d0 + d1 * d1;
            }
        }
        #pragma unroll
        for (int o = 16; o; o >>= 1) var += __shfl_xor_sync(0xffffffffu, var, o);
        float rstd = rsqrtf(var / (float)dim + 1e-5f);
        #pragma unroll
        for (int i = 0; i < 5; i++) {
            if (i >= cnt) break;
            int p = lane + i * 32;
            if (p < npair) {
                float2 ww = *reinterpret_cast<const float2*>(w + 2 * p);
                float2 bb = *reinterpret_cast<const float2*>(b + 2 * p);
                float o0 = (v0[i] - mu) * rstd * ww.x + bb.x;
                float o1 = (v1[i] - mu) * rstd * ww.y + bb.y;
                *reinterpret_cast<__nv_bfloat162*>(&orow[2 * p]) =
                    __floats2bfloat162_rn(o0, o1);
            }
        }
    } else {
        float v[9];
        int cnt = (dim + 31) >> 5;
        float s = 0.f;
        #pragma unroll
        for (int i = 0; i < 9; i++) {
            if (i >= cnt) break;
            int d = lane + i * 32;
            v[i] = (d < dim) ? r[d] : 0.f;
            s += v[i];
        }
        #pragma unroll
        for (int o = 16; o; o >>= 1) s += __shfl_xor_sync(0xffffffffu, s, o);
        float mu = s / (float)dim;
        float var = 0.f;
        #pragma unroll
        for (int i = 0; i < 9; i++) {
            if (i >= cnt) break;
            int d = lane + i * 32;
            float dv = (d < dim) ? v[i] - mu : 0.f;
            var += dv * dv;
        }
        #pragma unroll
        for (int o = 16; o; o >>= 1) var += __shfl_xor_sync(0xffffffffu, var, o);
        float rstd = rsqrtf(var / (float)dim + 1e-5f);
        #pragma unroll
        for (int i = 0; i < 9; i++) {
            if (i >= cnt) break;
            int d = lane + i * 32;
            if (d < dim) orow[d] = __float2bfloat16((v[i] - mu) * rstd * w[d] + b[d]);
        }
    }
}

// LayerNorm (dim 256) + concat residual channel -> f32 rows of dim 257
__global__ void ln_concat_kernel(const float* __restrict__ in, float* __restrict__ out,
                                 const float* __restrict__ w, const float* __restrict__ b,
                                 const float* __restrict__ res) {
    int row  = (blockIdx.x * blockDim.x + threadIdx.x) >> 5;
    int lane = threadIdx.x & 31;
    if (row >= NT) return;
    const float* r = in + (size_t)row * 256;
    float v[8];
    float s = 0.f;
    #pragma unroll
    for (int i = 0; i < 8; i++) { v[i] = r[lane + i * 32]; s += v[i]; }
    #pragma unroll
    for (int o = 16; o; o >>= 1) s += __shfl_xor_sync(0xffffffffu, s, o);
    float mu = s * (1.f / 256.f);
    float var = 0.f;
    #pragma unroll
    for (int i = 0; i < 8; i++) { float dv = v[i] - mu; var += dv * dv; }
    #pragma unroll
    for (int o = 16; o; o >>= 1) var += __shfl_xor_sync(0xffffffffu, var, o);
    float rstd = rsqrtf(var * (1.f / 256.f) + 1e-5f);
    float* orow = out + (size_t)row * 257;
    #pragma unroll
    for (int i = 0; i < 8; i++) {
        int d = lane + i * 32;
        orow[d] = (v[i] - mu) * rstd * w[d] + b[d];
    }
    if (lane == 0) orow[256] = res[row];
}

// ---------------------------------------------------------------------------
// bf16 cp.async GEMM (r14-proven): BM=128 BN=64 BK=32, 3-stage cp.async,
// ldmatrix.x4 fragment loads, packed epilogue stores, __launch_bounds__(256,4).
// MODE 0: C[M,N] f32 store
// MODE 1: C[M,N] f32 accumulate (float2 when N even)
// MODE 2: dt path: edb = half2(exp(-sp), sp*u), exp(-sp) via sigmoid identity
// MODE 3: C f32 store + bf16x2 copy of cols<side_r into side
// MODE 4: bf16x2 store into side (ld side_ld), no f32
// ---------------------------------------------------------------------------
__device__ __forceinline__ void mma_bf16(float* c, const unsigned* a, const unsigned* b) {
    asm volatile(
        "mma.sync.aligned.m16n8k16.row.col.f32.bf16.bf16.f32 "
        "{%0,%1,%2,%3}, {%4,%5,%6,%7}, {%8,%9}, {%0,%1,%2,%3};"
        : "+f"(c[0]), "+f"(c[1]), "+f"(c[2]), "+f"(c[3])
        : "r"(a[0]), "r"(a[1]), "r"(a[2]), "r"(a[3]), "r"(b[0]), "r"(b[1]));
}

__device__ __forceinline__ void cpasync16(void* smem, const void* gmem) {
    unsigned saddr = (unsigned)__cvta_generic_to_shared(smem);
    asm volatile("cp.async.cg.shared.global [%0], [%1], 16;\n" :: "r"(saddr), "l"(gmem));
}

__device__ __forceinline__ void ldsm_x4(unsigned& r0, unsigned& r1,
                                        unsigned& r2, unsigned& r3, unsigned addr) {
    asm volatile("ldmatrix.sync.aligned.m8n8.x4.shared.b16 {%0,%1,%2,%3}, [%4];"
                 : "=r"(r0), "=r"(r1), "=r"(r2), "=r"(r3) : "r"(addr));
}

#define SWZ(row, c) (((((c) >> 2) ^ (((row) >> 1) & 3)) << 2) + ((c) & 3))

template <int MODE>
__global__ __launch_bounds__(256, 4)
void gemm_bf16_async(const __nv_bfloat16* __restrict__ A,
                     const __nv_bfloat16* __restrict__ W,
                     float* __restrict__ C, int M, int N, int Kpad,
                     const float* __restrict__ bias,
                     __nv_bfloat16* __restrict__ side, int side_ld, int side_r,
                     const __nv_bfloat16* __restrict__ ubf, int u_ld,
                     __half2* __restrict__ edb) {
    __shared__ unsigned As[GSTAGES][128 * 16];
    __shared__ unsigned Bs[GSTAGES][64 * 16];

    int tid  = threadIdx.x;
    int lane = tid & 31;
    int warp = tid >> 5;
    int wm = warp & 3, wn = warp >> 2;
    int g = lane >> 2, tg = lane & 3;
    int bm = blockIdx.y * 128;
    int bn = blockIdx.x * 64;
    int ntile = Kpad >> 5;

    int tq = lane >> 3, rl = lane & 7;
    unsigned as_base = (unsigned)__cvta_generic_to_shared(&As[0][0]);
    unsigned bs_base = (unsigned)__cvta_generic_to_shared(&Bs[0][0]);
    int rowA[2];
    rowA[0] = wm * 32 + 0  + (tq & 1) * 8 + rl;
    rowA[1] = wm * 32 + 16 + (tq & 1) * 8 + rl;
    int chA = tq >> 1;
    int colB[2];
    colB[0] = wn * 32 + 0  + (tq >> 1) * 8 + rl;
    colB[1] = wn * 32 + 16 + (tq >> 1) * 8 + rl;
    int chB = tq & 1;

    float acc[2][4][4];
    #pragma unroll
    for (int mt = 0; mt < 2; mt++)
        #pragma unroll
        for (int nt = 0; nt < 4; nt++)
            #pragma unroll
            for (int i = 0; i < 4; i++) acc[mt][nt][i] = 0.f;

    auto issue = [&](int buf, int t) {
        int k0 = t << 5;
        #pragma unroll
        for (int i = 0; i < 2; i++) {
            int idx = i * 256 + tid;
            int row = idx >> 2, ch = idx & 3;
            cpasync16(&As[buf][row * 16 + ((ch ^ ((row >> 1) & 3)) << 2)],
                      A + (size_t)(bm + row) * Kpad + k0 + ch * 8);
        }
        {
            int row = tid >> 2, ch = tid & 3;
            cpasync16(&Bs[buf][row * 16 + ((ch ^ ((row >> 1) & 3)) << 2)],
                      W + (size_t)(bn + row) * Kpad + k0 + ch * 8);
        }
        asm volatile("cp.async.commit_group;\n");
    };

    #pragma unroll
    for (int t = 0; t < GSTAGES - 1; t++) {
        if (t < ntile) issue(t, t);
        else asm volatile("cp.async.commit_group;\n");
    }

    for (int t = 0; t < ntile; t++) {
        asm volatile("cp.async.wait_group 1;\n");
        __syncthreads();
        int tn = t + GSTAGES - 1;
        if (tn < ntile) issue(tn % GSTAGES, tn);
        else asm volatile("cp.async.commit_group;\n");

        int buf = t % GSTAGES;
        unsigned abuf = as_base + (unsigned)(buf * 128 * 16 * 4);
        unsigned bbuf = bs_base + (unsigned)(buf * 64 * 16 * 4);
        #pragma unroll
        for (int ks = 0; ks < 2; ks++) {
            unsigned afr[2][4], bfr[4][2];
            #pragma unroll
            for (int mt = 0; mt < 2; mt++) {
                int r = rowA[mt];
                int ch = ks * 2 + chA;
                unsigned off = (unsigned)(r * 16 + ((ch ^ ((r >> 1) & 3)) << 2)) * 4u;
                ldsm_x4(afr[mt][0], afr[mt][1], afr[mt][2], afr[mt][3], abuf + off);
            }
            #pragma unroll
            for (int p = 0; p < 2; p++) {
                int cc = colB[p];
                int ch = ks * 2 + chB;
                unsigned off = (unsigned)(cc * 16 + ((ch ^ ((cc >> 1) & 3)) << 2)) * 4u;
                ldsm_x4(bfr[2 * p][0], bfr[2 * p][1],
                        bfr[2 * p + 1][0], bfr[2 * p + 1][1], bbuf + off);
            }
            #pragma unroll
            for (int mt = 0; mt < 2; mt++)
                #pragma unroll
                for (int nt = 0; nt < 4; nt++)
                    mma_bf16(acc[mt][nt], afr[mt], bfr[nt]);
        }
    }

    // epilogue — packed column-pair stores
    #pragma unroll
    for (int mt = 0; mt < 2; mt++) {
        int row0 = bm + wm * 32 + mt * 16 + g;
        #pragma unroll
        for (int nt = 0; nt < 4; nt++) {
            int col = bn + wn * 32 + nt * 8 + tg * 2;   // always even
            float* c = acc[mt][nt];
            #pragma unroll
            for (int rr = 0; rr < 2; rr++) {
                int ro = row0 + rr * 8;
                float v0 = c[rr * 2 + 0];
                float v1 = c[rr * 2 + 1];
                if (MODE == 0) {
                    if (col < N)     C[(size_t)ro * N + col]     = v0;
                    if (col + 1 < N) C[(size_t)ro * N + col + 1] = v1;
                }
                if (MODE == 1) {
                    if ((N & 1) == 0) {
                        if (col < N) {
                            float2* p = reinterpret_cast<float2*>(&C[(size_t)ro * N + col]);
                            float2 o = *p;
                            o.x += v0; o.y += v1;
                            *p = o;
                        }
                    } else {
                        if (col < N)     { size_t ix = (size_t)ro * N + col;     C[ix] += v0; }
                        if (col + 1 < N) { size_t ix = (size_t)ro * N + col + 1; C[ix] += v1; }
                    }
                }
                if (MODE == 2) {
                    if (col < N) {   // N even; col even -> col+1 < N too
                        float x0 = v0 + bias[col];
                        float x1 = v1 + bias[col + 1];
                        float q0 = __expf(-fabsf(x0));
                        float q1 = __expf(-fabsf(x1));
                        float sp0 = fmaxf(x0, 0.f) + log1pf(q0);
                        float sp1 = fmaxf(x1, 0.f) + log1pf(q1);
                        // exp(-softplus(x)) == (x>=0 ? q : 1) / (1+q)  (exact)
                        float e0 = (x0 >= 0.f ? q0 : 1.f) / (1.f + q0);
                        float e1 = (x1 >= 0.f ? q1 : 1.f) / (1.f + q1);
                        __nv_bfloat162 uu = *reinterpret_cast<const __nv_bfloat162*>(
                            &ubf[(size_t)ro * u_ld + col]);
                        float u0 = __bfloat162float(uu.x);
                        float u1 = __bfloat162float(uu.y);
                        __half2 p0 = __floats2half2_rn(e0, sp0 * u0);
                        __half2 p1 = __floats2half2_rn(e1, sp1 * u1);
                        uint2 pk;
                        pk.x = *reinterpret_cast<unsigned*>(&p0);
                        pk.y = *reinterpret_cast<unsigned*>(&p1);
                        *reinterpret_cast<uint2*>(&edb[(size_t)ro * N + col]) = pk;
                    }
                }
                if (MODE == 3) {
                    if (col < N)     C[(size_t)ro * N + col]     = v0;
                    if (col + 1 < N) C[(size_t)ro * N + col + 1] = v1;
                    if (col < side_r) {
                        *reinterpret_cast<__nv_bfloat162*>(
                            &side[(size_t)ro * side_ld + col]) =
                            __floats2bfloat162_rn(v0, v1);
                    }
                }
                if (MODE == 4) {
                    if (col < N) {   // N even
                        *reinterpret_cast<__nv_bfloat162*>(
                            &side[(size_t)ro * side_ld + col]) =
                            __floats2bfloat162_rn(v0, v1);
                    }
                }
            }
        }
    }
}

// ---------------------------------------------------------------------------
// Fused depthwise causal conv1d (K=4) + SiLU + z-gate precompute (r14-proven).
// Channel-PAIR: bf16x2 smem reads, bf16x2 x_bf store, 8B uz store.
// ---------------------------------------------------------------------------
__global__ void conv_fused_kernel(const __nv_bfloat16* __restrict__ xz, int ld_xz,
                                  const float* __restrict__ cw,
                                  const float* __restrict__ cb,
                                  const float* __restrict__ Dp,
                                  __nv_bfloat16* __restrict__ x_bf, int ld_xbf,
                                  __half2* __restrict__ uz,
                                  int di) {
    __shared__ __nv_bfloat16 sx[CTOK + 3][128];
    __shared__ float scw[4][128], scb[128], sD[128];
    int tid = threadIdx.x;
    int c0 = blockIdx.x * 128;
    int t0 = blockIdx.y * CTOK;
    int l0 = t0 & (SEQ - 1);

    if (tid < 128) {
        int ch = c0 + tid;
        bool ok = ch < di;
        scb[tid] = ok ? cb[ch] : 0.f;
        sD[tid]  = ok ? Dp[ch] : 0.f;
        #pragma unroll
        for (int k = 0; k < 4; k++) scw[k][tid] = ok ? cw[ch * 4 + k] : 0.f;
    }
    for (int idx = tid; idx < (CTOK + 3) * 128; idx += 256) {
        int row = idx >> 7, chl = idx & 127;
        int ch = c0 + chl;
        int token = t0 - 3 + row;
        __nv_bfloat16 v = __float2bfloat16(0.f);
        if (ch < di && (row >= 3 || l0 > 0))
            v = xz[(size_t)token * ld_xz + ch];
        sx[row][chl] = v;
    }
    __syncthreads();

    int cp  = tid & 63;          // channel pair index
    int th  = tid >> 6;          // token group 0..3
    int chl = cp * 2;
    int c   = c0 + chl;
    if (c >= di) return;         // di even -> c+1 < di whenever c < di
    float w0a = scw[0][chl],     w1a = scw[1][chl],     w2a = scw[2][chl],     w3a = scw[3][chl];
    float w0b = scw[0][chl + 1], w1b = scw[1][chl + 1], w2b = scw[2][chl + 1], w3b = scw[3][chl + 1];
    float bba = scb[chl], bbb = scb[chl + 1];
    float Da  = sD[chl],  Db  = sD[chl + 1];

    for (int tt = 0; tt < CTOK / 4; tt++) {
        int tl = th * (CTOK / 4) + tt;
        size_t token = (size_t)t0 + tl;
        float2 x0 = __bfloat1622float2(*reinterpret_cast<const __nv_bfloat162*>(&sx[tl][chl]));
        float2 x1 = __bfloat1622float2(*reinterpret_cast<const __nv_bfloat162*>(&sx[tl + 1][chl]));
        float2 x2 = __bfloat1622float2(*reinterpret_cast<const __nv_bfloat162*>(&sx[tl + 2][chl]));
        float2 x3 = __bfloat1622float2(*reinterpret_cast<const __nv_bfloat162*>(&sx[tl + 3][chl]));
        float acc0 = bba + w0a * x0.x + w1a * x1.x + w2a * x2.x + w3a * x3.x;
        float acc1 = bbb + w0b * x0.y + w1b * x1.y + w2b * x2.y + w3b * x3.y;
        float u0 = acc0 / (1.f + __expf(-acc0));
        float u1 = acc1 / (1.f + __expf(-acc1));
        *reinterpret_cast<__nv_bfloat162*>(&x_bf[token * ld_xbf + c]) =
            __floats2bfloat162_rn(u0, u1);
        float2 zz = __bfloat1622float2(*reinterpret_cast<const __nv_bfloat162*>(
            &xz[token * ld_xz + di + c]));
        float zg0 = zz.x / (1.f + __expf(-zz.x));
        float zg1 = zz.y / (1.f + __expf(-zz.y));
        __half2 p0 = __floats2half2_rn(zg0, u0 * Da * zg0);
        __half2 p1 = __floats2half2_rn(zg1, u1 * Db * zg1);
        uint2 pk;
        pk.x = *reinterpret_cast<unsigned*>(&p0);
        pk.y = *reinterpret_cast<unsigned*>(&p1);
        *reinterpret_cast<uint2*>(&uz[token * di + c]) = pk;
    }
}

// ---------------------------------------------------------------------------
// Chunked parallel selective scan (r14-proven pass1/pass3; pass2 ILP-batched).
// ---------------------------------------------------------------------------
__global__ void scan_pass1(const __half2* __restrict__ edb,
                           const float* __restrict__ xdbl, int ld_xd, int r,
                           const float* __restrict__ A_log,
                           float* __restrict__ P, float* __restrict__ S,
                           int di) {
    __shared__ float sB[CHUNK][17];
    __shared__ float sA[128][17];
    int tid = threadIdx.x;
    int c0 = blockIdx.x * 128, chunk = blockIdx.y, b = blockIdx.z;
    size_t tok0 = (size_t)b * SEQ + (size_t)chunk * CHUNK;
    for (int i = tid; i < CHUNK * 16; i += 128) {
        int tt = i >> 4, s = i & 15;
        sB[tt][s] = xdbl[(tok0 + tt) * ld_xd + r + s];
    }
    for (int i = tid; i < 128 * 16; i += 128) {
        int cc = i >> 4, s = i & 15;
        int ch = c0 + cc;
        sA[cc][s] = (ch < di) ? A_log[(size_t)ch * 16 + s] : 0.f;
    }
    __syncthreads();
    int c = c0 + tid;
    if (c >= di) return;

    bool fast = true;
    float a[16];
    #pragma unroll
    for (int s = 0; s < 16; s++) {
        a[s] = -__expf(sA[tid][s]);
        fast = fast && (fabsf(a[s] + (float)(s + 1)) <= 1e-5f * (float)(s + 1));
    }
    float st[16];
    #pragma unroll
    for (int s = 0; s < 16; s++) st[s] = 0.f;
    size_t obase = ((size_t)(b * NCH + chunk) * 16) * di + c;

    if (fast) {
        float prodE = 1.f;
        for (int t = 0; t < CHUNK; t++) {
            size_t tok = tok0 + t;
            float2 ed = __half22float2(edb[tok * di + c]);
            float e = ed.x, db = ed.y;
            prodE *= e;
            float ep = 1.f;
            #pragma unroll
            for (int s = 0; s < 16; s++) {
                ep *= e;
                st[s] = ep * st[s] + db * sB[t][s];
            }
        }
        float pp = 1.f;
        #pragma unroll
        for (int s = 0; s < 16; s++) {
            pp *= prodE;
            P[obase + (size_t)s * di] = pp;
            S[obase + (size_t)s * di] = st[s];
        }
    } else {
        float Pl[16];
        #pragma unroll
        for (int s = 0; s < 16; s++) Pl[s] = 1.f;
        for (int t = 0; t < CHUNK; t++) {
            size_t tok = tok0 + t;
            float2 ed = __half22float2(edb[tok * di + c]);
            float e = ed.x, db = ed.y;
            #pragma unroll
            for (int s = 0; s < 16; s++) {
                float dA = __powf(e, -a[s]);
                st[s] = dA * st[s] + db * sB[t][s];
                Pl[s] *= dA;
            }
        }
        #pragma unroll
        for (int s = 0; s < 16; s++) {
            P[obase + (size_t)s * di] = Pl[s];
            S[obase + (size_t)s * di] = st[s];
        }
    }
}

// ILP-batched serial chunk combine: loads for 8 chunks issued before the
// dependent scan+store phase (MLP=16), breaking the store->load alias chain.
__global__ void scan_pass2(float* __restrict__ P, float* __restrict__ S, int di) {
    int per_b = 16 * di;
    int gi = blockIdx.x * blockDim.x + threadIdx.x;
    if (gi >= BATCH * per_b) return;
    int b = gi / per_b;
    int sc = gi - b * per_b;
    size_t base = (size_t)b * NCH * per_b + sc;
    float st = 0.f;
    #pragma unroll
    for (int cg = 0; cg < NCH; cg += 8) {
        float p[8], sv[8];
        #pragma unroll
        for (int j = 0; j < 8; j++) {
            size_t idx = base + (size_t)(cg + j) * per_b;
            p[j]  = P[idx];
            sv[j] = S[idx];
        }
        #pragma unroll
        for (int j = 0; j < 8; j++) {
            size_t idx = base + (size_t)(cg + j) * per_b;
            S[idx] = st;            // init state entering chunk cg+j
            st = p[j] * st + sv[j];
        }
    }
}

__global__ void scan_pass3(const __half2* __restrict__ edb,
                           const float* __restrict__ xdbl, int ld_xd, int r,
                           const float* __restrict__ A_log,
                           const float* __restrict__ S,
                           const __half2* __restrict__ uz,
                           __nv_bfloat16* __restrict__ yg, int ld_yg,
                           int di) {
    __shared__ float sBC[CHUNK][33];
    __shared__ float sA[128][17];
    int tid = threadIdx.x;
    int c0 = blockIdx.x * 128, chunk = blockIdx.y, b = blockIdx.z;
    size_t tok0 = (size_t)b * SEQ + (size_t)chunk * CHUNK;
    for (int i = tid; i < CHUNK * 32; i += 128) {
        int tt = i >> 5, s = i & 31;
        sBC[tt][s] = xdbl[(tok0 + tt) * ld_xd + r + s];
    }
    for (int i = tid; i < 128 * 16; i += 128) {
        int cc = i >> 4, s = i & 15;
        int ch = c0 + cc;
        sA[cc][s] = (ch < di) ? A_log[(size_t)ch * 16 + s] : 0.f;
    }
    __syncthreads();
    int c = c0 + tid;
    if (c >= di) return;

    bool fast = true;
    float a[16];
    #pragma unroll
    for (int s = 0; s < 16; s++) {
        a[s] = -__expf(sA[tid][s]);
        fast = fast && (fabsf(a[s] + (float)(s + 1)) <= 1e-5f * (float)(s + 1));
    }
    float st[16];
    size_t sbase = ((size_t)(b * NCH + chunk) * 16) * di + c;
    #pragma unroll
    for (int s = 0; s < 16; s++) st[s] = S[sbase + (size_t)s * di];

    if (fast) {
        for (int t = 0; t < CHUNK; t++) {
            size_t tok = tok0 + t;
            float2 ed = __half22float2(edb[tok * di + c]);
            float e = ed.x, db = ed.y;
            float y = 0.f, ep = 1.f;
            #pragma unroll
            for (int s = 0; s < 16; s++) {
                ep *= e;
                st[s] = ep * st[s] + db * sBC[t][s];
                y += st[s] * sBC[t][16 + s];
            }
            float2 g = __half22float2(uz[tok * di + c]);
            yg[tok * ld_yg + c] = __float2bfloat16(y * g.x + g.y);
        }
    } else {
        for (int t = 0; t < CHUNK; t++) {
            size_t tok = tok0 + t;
            float2 ed = __half22float2(edb[tok * di + c]);
            float e = ed.x, db = ed.y;
            float y = 0.f;
            #pragma unroll
            for (int s = 0; s < 16; s++) {
                float dA = __powf(e, -a[s]);
                st[s] = dA * st[s] + db * sBC[t][s];
                y += st[s] * sBC[t][16 + s];
            }
            float2 g = __half22float2(uz[tok * di + c]);
            yg[tok * ld_yg + c] = __float2bfloat16(y * g.x + g.y);
        }
    }
}

// ---------------------------------------------------------------------------
// Mean pool + classifier
// ---------------------------------------------------------------------------
__global__ void pool_kernel(const float* __restrict__ hn, float* __restrict__ pool) {
    int b = blockIdx.x, dd = blockIdx.y;
    float s = 0.f;
    for (int l = threadIdx.x; l < SEQ; l += 128)
        s += hn[((size_t)b * SEQ + l) * 257 + dd];
    __shared__ float red[128];
    red[threadIdx.x] = s;
    __syncthreads();
    for (int o = 64; o; o >>= 1) {
        if (threadIdx.x < o) red[threadIdx.x] += red[threadIdx.x + o];
        __syncthreads();
    }
    if (threadIdx.x == 0) pool[b * 257 + dd] = red[0] * (1.f / (float)SEQ);
}

__global__ void cls_kernel(const float* __restrict__ pool,
                           const float* __restrict__ w,
                           const float* __restrict__ bias,
                           float* __restrict__ out) {
    int i = threadIdx.x;
    if (i >= BATCH * 16) return;
    int b = i >> 4, n = i & 15;
    float acc = bias[n];
    for (int dd = 0; dd < 257; dd++) acc += pool[b * 257 + dd] * w[n * 257 + dd];
    out[b * 16 + n] = acc;
}

// ---------------------------------------------------------------------------
// Host orchestration
// ---------------------------------------------------------------------------
static inline int align32(int x) { return (x + 31) & ~31; }

static inline void launch_gemm(const __nv_bfloat16* A, const __nv_bfloat16* W,
                               float* C, int M, int N, int Kpad, int mode,
                               const float* bias = nullptr,
                               __nv_bfloat16* side = nullptr, int side_ld = 0,
                               int side_r = 0,
                               const __nv_bfloat16* ubf = nullptr, int u_ld = 0,
                               __half2* edb = nullptr) {
    dim3 grid((N + 63) / 64, M / 128);
    switch (mode) {
    case 0: gemm_bf16_async<0><<<grid, 256>>>(A, W, C, M, N, Kpad, bias, side, side_ld, side_r, ubf, u_ld, edb); break;
    case 1: gemm_bf16_async<1><<<grid, 256>>>(A, W, C, M, N, Kpad, bias, side, side_ld, side_r, ubf, u_ld, edb); break;
    case 2: gemm_bf16_async<2><<<grid, 256>>>(A, W, C, M, N, Kpad, bias, side, side_ld, side_r, ubf, u_ld, edb); break;
    case 3: gemm_bf16_async<3><<<grid, 256>>>(A, W, C, M, N, Kpad, bias, side, side_ld, side_r, ubf, u_ld, edb); break;
    default: gemm_bf16_async<4><<<grid, 256>>>(A, W, C, M, N, Kpad, bias, side, side_ld, side_r, ubf, u_ld, edb); break;
    }
}

static void mamba_block(float* hbuf, int d, int di, int r,
                        const float* ln_w, const float* ln_b,
                        const float* conv_w, const float* conv_b,
                        const float* dt_b, const float* A_log, const float* Dp,
                        const __nv_bfloat16* w_in, const __nv_bfloat16* w_xp,
                        const __nv_bfloat16* w_dt, const __nv_bfloat16* w_out,
                        __nv_bfloat16* hn_bf, __nv_bfloat16* xz_bf,
                        __nv_bfloat16* x_bf, float* xdbl, __nv_bfloat16* xdbl_bf,
                        __half2* edb, __half2* uz,
                        __nv_bfloat16* yg_bf, float* Pbuf, float* Sbuf) {
    int xdw = r + 2 * DSTATE;
    int dpad = align32(d), dipad = align32(di);

    ln_bf16_kernel<<<NT / 8, 256>>>(hbuf, hn_bf, ln_w, ln_b, d, dpad);
    // in-proj -> xz bf16 only
    launch_gemm(hn_bf, w_in, nullptr, NT, 2 * di, dpad, 4,
                nullptr, xz_bf, 1056, 0);
    // fused conv + silu + z-gate precompute
    conv_fused_kernel<<<dim3((di + 127) / 128, NT / CTOK), 256>>>(
        xz_bf, 1056, conv_w, conv_b, Dp, x_bf, dipad, uz, di);
    // x-proj -> xdbl f32 + bf16 side (dt_r part)
    launch_gemm(x_bf, w_xp, xdbl, NT, xdw, dipad, 3,
                nullptr, xdbl_bf, 32, r);
    // dt path: edb = half2(exp(-softplus), dt*u)
    launch_gemm(xdbl_bf, w_dt, nullptr, NT, di, 32, 2,
                dt_b, nullptr, 0, 0, x_bf, dipad, edb);
    // chunked parallel scan
    dim3 sg((di + 127) / 128, NCH, BATCH);
    scan_pass1<<<sg, 128>>>(edb, xdbl, xdw, r, A_log, Pbuf, Sbuf, di);
    scan_pass2<<<(BATCH * 16 * di + 255) / 256, 256>>>(Pbuf, Sbuf, di);
    scan_pass3<<<sg, 128>>>(edb, xdbl, xdw, r, A_log, Sbuf,
                            uz, yg_bf, dipad, di);
    // out-proj with fused residual add
    launch_gemm(yg_bf, w_out, hbuf, NT, d, dipad, 1);
}

extern "C" void kernel_launch(void* const* d_in, const int* in_sizes, int n_in,
                              void* d_out, int out_size) {
    const int*   x         = (const int*)  d_in[0];
    const float* emb       = (const float*)d_in[1];
    const float* blk_ln_w  = (const float*)d_in[2];
    const float* blk_ln_b  = (const float*)d_in[3];
    const float* blk_in_w  = (const float*)d_in[4];
    const float* blk_cv_w  = (const float*)d_in[5];
    const float* blk_cv_b  = (const float*)d_in[6];
    const float* blk_xp_w  = (const float*)d_in[7];
    const float* blk_dt_w  = (const float*)d_in[8];
    const float* blk_dt_b  = (const float*)d_in[9];
    const float* blk_A_log = (const float*)d_in[10];
    const float* blk_D     = (const float*)d_in[11];
    const float* blk_out_w = (const float*)d_in[12];
    const float* norm_w    = (const float*)d_in[13];
    const float* norm_b    = (const float*)d_in[14];
    const float* cmb_ln_w  = (const float*)d_in[15];
    const float* cmb_ln_b  = (const float*)d_in[16];
    const float* cmb_in_w  = (const float*)d_in[17];
    const float* cmb_cv_w  = (const float*)d_in[18];
    const float* cmb_cv_b  = (const float*)d_in[19];
    const float* cmb_xp_w  = (const float*)d_in[20];
    const float* cmb_dt_w  = (const float*)d_in[21];
    const float* cmb_dt_b  = (const float*)d_in[22];
    const float* cmb_A_log = (const float*)d_in[23];
    const float* cmb_D     = (const float*)d_in[24];
    const float* cmb_out_w = (const float*)d_in[25];
    const float* fin_w     = (const float*)d_in[26];
    const float* fin_b     = (const float*)d_in[27];
    const float* cls_w     = (const float*)d_in[28];
    const float* cls_b     = (const float*)d_in[29];
    float* out = (float*)d_out;

    float *p_h, *p_hc, *p_hn, *p_xdbl, *p_res, *p_pool, *p_P, *p_S;
    __nv_bfloat16 *p_hn_bf, *p_xz_bf, *p_x_bf, *p_xdbl_bf, *p_yg_bf, *p_wbf;
    __half2 *p_edb, *p_uz;
    cudaGetSymbolAddress((void**)&p_h,       g_h);
    cudaGetSymbolAddress((void**)&p_hc,      g_hc);
    cudaGetSymbolAddress((void**)&p_hn,      g_hn);
    cudaGetSymbolAddress((void**)&p_hn_bf,   g_hn_bf);
    cudaGetSymbolAddress((void**)&p_xz_bf,   g_xz_bf);
    cudaGetSymbolAddress((void**)&p_x_bf,    g_x_bf);
    cudaGetSymbolAddress((void**)&p_xdbl,    g_xdbl);
    cudaGetSymbolAddress((void**)&p_xdbl_bf, g_xdbl_bf);
    cudaGetSymbolAddress((void**)&p_edb,     g_edb);
    cudaGetSymbolAddress((void**)&p_uz,      g_uz);
    cudaGetSymbolAddress((void**)&p_yg_bf,   g_yg_bf);
    cudaGetSymbolAddress((void**)&p_res,     g_res);
    cudaGetSymbolAddress((void**)&p_pool,    g_pool);
    cudaGetSymbolAddress((void**)&p_P,       g_P);
    cudaGetSymbolAddress((void**)&p_S,       g_S);
    cudaGetSymbolAddress((void**)&p_wbf,     g_wbf);

    // -------- weight table (deterministic offsets) --------
    WTab tab;
    long long off = 0;
    int wi = 0;
    long long w_in_off[5], w_xp_off[5], w_dt_off[5], w_out_off[5];
    auto add = [&](const float* src, int N, int K) -> long long {
        int Kp = align32(K);
        int Np = (N + 63) & ~63;
        long long o = off;
        tab.w[wi].src = src; tab.w[wi].off = o;
        tab.w[wi].N = N; tab.w[wi].K = K; tab.w[wi].Kpad = Kp;
        tab.w[wi].total = Np * Kp;
        wi++;
        off += (long long)Np * Kp;
        return o;
    };
    for (int i = 0; i < 4; i++) {
        w_in_off[i]  = add(blk_in_w  + (size_t)i * 1024 * 256, 1024, 256);
        w_xp_off[i]  = add(blk_xp_w  + (size_t)i * 48 * 512,   48,  512);
        w_dt_off[i]  = add(blk_dt_w  + (size_t)i * 512 * 16,   512, 16);
        w_out_off[i] = add(blk_out_w + (size_t)i * 256 * 512,  256, 512);
    }
    w_in_off[4]  = add(cmb_in_w,  1028, 257);
    w_xp_off[4]  = add(cmb_xp_w,  49,  514);
    w_dt_off[4]  = add(cmb_dt_w,  514, 17);
    w_out_off[4] = add(cmb_out_w, 257, 514);

    wconv_kernel<<<dim3(1224, 20), 256>>>(tab, p_wbf);
    embed_kernel<<<NT, 64>>>(x, emb, p_h, p_res);

    for (int i = 0; i < 4; i++) {
        mamba_block(p_h, 256, 512, 16,
                    blk_ln_w + (size_t)i * 256, blk_ln_b + (size_t)i * 256,
                    blk_cv_w + (size_t)i * 512 * 4, blk_cv_b + (size_t)i * 512,
                    blk_dt_b + (size_t)i * 512,
                    blk_A_log + (size_t)i * 512 * 16, blk_D + (size_t)i * 512,
                    p_wbf + w_in_off[i], p_wbf + w_xp_off[i],
                    p_wbf + w_dt_off[i], p_wbf + w_out_off[i],
                    p_hn_bf, p_xz_bf, p_x_bf, p_xdbl, p_xdbl_bf,
                    p_edb, p_uz, p_yg_bf, p_P, p_S);
    }

    ln_concat_kernel<<<NT / 8, 256>>>(p_h, p_hc, norm_w, norm_b, p_res);

    mamba_block(p_hc, 257, 514, 17,
                cmb_ln_w, cmb_ln_b, cmb_cv_w, cmb_cv_b, cmb_dt_b,
                cmb_A_log, cmb_D,
                p_wbf + w_in_off[4], p_wbf + w_xp_off[4],
                p_wbf + w_dt_off[4], p_wbf + w_out_off[4],
                p_hn_bf, p_xz_bf, p_x_bf, p_xdbl, p_xdbl_bf,
                p_edb, p_uz, p_yg_bf, p_P, p_S);

    ln_kernel<<<NT / 8, 256>>>(p_hc, p_hn, fin_w, fin_b, 257, NT);
    pool_kernel<<<dim3(BATCH, 257), 128>>>(p_hn, p_pool);
    cls_kernel<<<1, 128>>>(p_pool, cls_w, cls_b, out);
}

// round 17
// speedup vs baseline: 1.1182x; 1.0052x over previous
#include <cuda_runtime.h>
#include <cuda_bf16.h>
#include <cuda_fp16.h>
#include <cstddef>

// ---------------------------------------------------------------------------
// Problem constants
// ---------------------------------------------------------------------------
#define BATCH   8
#define SEQ     4096
#define NT      (BATCH * SEQ)      // 32768 tokens
#define DSTATE  16
#define DCONV   4
#define CHUNK   128
#define NCH     (SEQ / CHUNK)      // 32 chunks
#define GSTAGES 3
#define CTOK    64                 // conv token tile
// main blocks: d=256, di=512, r=16, xdw=48
// cmb block:   d=257, di=514, r=17, xdw=49

// ---------------------------------------------------------------------------
// Scratch (device globals — allocation-free)
// ---------------------------------------------------------------------------
__device__ float g_h   [(size_t)NT * 256];
__device__ float g_hc  [(size_t)NT * 257];
__device__ float g_hn  [(size_t)NT * 257];                       // final LN f32
__device__ __align__(16) __nv_bfloat16 g_hn_bf[(size_t)NT * 288];
__device__ __align__(16) __nv_bfloat16 g_xz_bf[(size_t)NT * 1056];
__device__ __align__(16) __nv_bfloat16 g_x_bf [(size_t)NT * 544];
__device__ float g_xdbl[(size_t)NT * 49];
__device__ __align__(16) __nv_bfloat16 g_xdbl_bf[(size_t)NT * 32];
__device__ __align__(16) __half2 g_edb[(size_t)NT * 514];        // (e, db) packed
__device__ __align__(16) __half2 g_uz [(size_t)NT * 514];        // (zg, ug) packed
__device__ __align__(16) __nv_bfloat16 g_yg_bf[(size_t)NT * 544];
__device__ float g_res [(size_t)NT];
__device__ float g_pool[(size_t)BATCH * 257];
__device__ float g_P [(size_t)BATCH * NCH * 16 * 514];
__device__ float g_S [(size_t)BATCH * NCH * 16 * 514];
__device__ __align__(16) __nv_bfloat16 g_wbf[2400000];           // padded bf16 weights

// ---------------------------------------------------------------------------
// Weight conversion: f32 (N,K) row-major -> bf16 (Npad, Kpad) zero-padded
// ---------------------------------------------------------------------------
struct WDesc { const float* src; long long off; int N, K, Kpad, total; };
struct WTab  { WDesc w[20]; };

__global__ void wconv_kernel(WTab tab, __nv_bfloat16* __restrict__ dst) {
    WDesc d = tab.w[blockIdx.y];
    int idx = blockIdx.x * 256 + threadIdx.x;
    if (idx >= d.total) return;
    int n = idx / d.Kpad;
    int k = idx - n * d.Kpad;
    float v = (n < d.N && k < d.K) ? d.src[(size_t)n * d.K + k] : 0.f;
    dst[d.off + idx] = __float2bfloat16(v);
}

// ---------------------------------------------------------------------------
// Embedding + residual channel (float4 copy)
// ---------------------------------------------------------------------------
__global__ void embed_kernel(const int* __restrict__ x,
                             const float* __restrict__ emb,
                             float* __restrict__ h, float* __restrict__ res) {
    int t = blockIdx.x;
    int id = x[t];
    const float4* e = reinterpret_cast<const float4*>(emb + (size_t)id * 256);
    float4* hr = reinterpret_cast<float4*>(h + (size_t)t * 256);
    int i = threadIdx.x;          // 64 threads, one float4 each
    hr[i] = e[i];
    if (i == 0) res[t] = (float)id;
}

// ---------------------------------------------------------------------------
// LayerNorm (f32 out): one warp per row
// ---------------------------------------------------------------------------
__global__ void ln_kernel(const float* __restrict__ in, float* __restrict__ out,
                          const float* __restrict__ w, const float* __restrict__ b,
                          int dim, int ntok) {
    int row  = (blockIdx.x * blockDim.x + threadIdx.x) >> 5;
    int lane = threadIdx.x & 31;
    if (row >= ntok) return;
    const float* r = in + (size_t)row * dim;
    float v[9];
    int cnt = (dim + 31) >> 5;
    float s = 0.f;
    #pragma unroll
    for (int i = 0; i < 9; i++) {
        if (i >= cnt) break;
        int d = lane + i * 32;
        v[i] = (d < dim) ? r[d] : 0.f;
        s += v[i];
    }
    #pragma unroll
    for (int o = 16; o; o >>= 1) s += __shfl_xor_sync(0xffffffffu, s, o);
    float mu = s / (float)dim;
    float var = 0.f;
    #pragma unroll
    for (int i = 0; i < 9; i++) {
        if (i >= cnt) break;
        int d = lane + i * 32;
        float dv = (d < dim) ? v[i] - mu : 0.f;
        var += dv * dv;
    }
    #pragma unroll
    for (int o = 16; o; o >>= 1) var += __shfl_xor_sync(0xffffffffu, var, o);
    float rstd = rsqrtf(var / (float)dim + 1e-5f);
    float* orow = out + (size_t)row * dim;
    #pragma unroll
    for (int i = 0; i < 9; i++) {
        if (i >= cnt) break;
        int d = lane + i * 32;
        if (d < dim) orow[d] = (v[i] - mu) * rstd * w[d] + b[d];
    }
}

// LayerNorm (bf16 out, padded ld).
// EVEN dim: channel-pair packed; ODD dim: scalar path (alignment).
__global__ void ln_bf16_kernel(const float* __restrict__ in,
                               __nv_bfloat16* __restrict__ out,
                               const float* __restrict__ w, const float* __restrict__ b,
                               int dim, int ldo) {
    int row  = (blockIdx.x * blockDim.x + threadIdx.x) >> 5;
    int lane = threadIdx.x & 31;
    if (row >= NT) return;
    const float* r = in + (size_t)row * dim;
    __nv_bfloat16* orow = out + (size_t)row * ldo;

    if ((dim & 1) == 0) {
        int npair = dim >> 1;
        int cnt = (npair + 31) >> 5;      // <= 5 for dim <= 320
        float v0[5], v1[5];
        float s = 0.f;
        #pragma unroll
        for (int i = 0; i < 5; i++) {
            if (i >= cnt) break;
            int p = lane + i * 32;
            if (p < npair) {
                float2 t = *reinterpret_cast<const float2*>(r + 2 * p);
                v0[i] = t.x; v1[i] = t.y;
            } else { v0[i] = 0.f; v1[i] = 0.f; }
            s += v0[i] + v1[i];
        }
        #pragma unroll
        for (int o = 16; o; o >>= 1) s += __shfl_xor_sync(0xffffffffu, s, o);
        float mu = s / (float)dim;
        float var = 0.f;
        #pragma unroll
        for (int i = 0; i < 5; i++) {
            if (i >= cnt) break;
            int p = lane + i * 32;
            if (p < npair) {
                float d0 = v0[i] - mu, d1 = v1[i] - mu;
                var += d0 * d0 + d1 * d1;
            }
        }
        #pragma unroll
        for (int o = 16; o; o >>= 1) var += __shfl_xor_sync(0xffffffffu, var, o);
        float rstd = rsqrtf(var / (float)dim + 1e-5f);
        #pragma unroll
        for (int i = 0; i < 5; i++) {
            if (i >= cnt) break;
            int p = lane + i * 32;
            if (p < npair) {
                float2 ww = *reinterpret_cast<const float2*>(w + 2 * p);
                float2 bb = *reinterpret_cast<const float2*>(b + 2 * p);
                float o0 = (v0[i] - mu) * rstd * ww.x + bb.x;
                float o1 = (v1[i] - mu) * rstd * ww.y + bb.y;
                *reinterpret_cast<__nv_bfloat162*>(&orow[2 * p]) =
                    __floats2bfloat162_rn(o0, o1);
            }
        }
    } else {
        float v[9];
        int cnt = (dim + 31) >> 5;
        float s = 0.f;
        #pragma unroll
        for (int i = 0; i < 9; i++) {
            if (i >= cnt) break;
            int d = lane + i * 32;
            v[i] = (d < dim) ? r[d] : 0.f;
            s += v[i];
        }
        #pragma unroll
        for (int o = 16; o; o >>= 1) s += __shfl_xor_sync(0xffffffffu, s, o);
        float mu = s / (float)dim;
        float var = 0.f;
        #pragma unroll
        for (int i = 0; i < 9; i++) {
            if (i >= cnt) break;
            int d = lane + i * 32;
            float dv = (d < dim) ? v[i] - mu : 0.f;
            var += dv * dv;
        }
        #pragma unroll
        for (int o = 16; o; o >>= 1) var += __shfl_xor_sync(0xffffffffu, var, o);
        float rstd = rsqrtf(var / (float)dim + 1e-5f);
        #pragma unroll
        for (int i = 0; i < 9; i++) {
            if (i >= cnt) break;
            int d = lane + i * 32;
            if (d < dim) orow[d] = __float2bfloat16((v[i] - mu) * rstd * w[d] + b[d]);
        }
    }
}

// LayerNorm (dim 256) + concat residual channel -> f32 rows of dim 257
__global__ void ln_concat_kernel(const float* __restrict__ in, float* __restrict__ out,
                                 const float* __restrict__ w, const float* __restrict__ b,
                                 const float* __restrict__ res) {
    int row  = (blockIdx.x * blockDim.x + threadIdx.x) >> 5;
    int lane = threadIdx.x & 31;
    if (row >= NT) return;
    const float* r = in + (size_t)row * 256;
    float v[8];
    float s = 0.f;
    #pragma unroll
    for (int i = 0; i < 8; i++) { v[i] = r[lane + i * 32]; s += v[i]; }
    #pragma unroll
    for (int o = 16; o; o >>= 1) s += __shfl_xor_sync(0xffffffffu, s, o);
    float mu = s * (1.f / 256.f);
    float var = 0.f;
    #pragma unroll
    for (int i = 0; i < 8; i++) { float dv = v[i] - mu; var += dv * dv; }
    #pragma unroll
    for (int o = 16; o; o >>= 1) var += __shfl_xor_sync(0xffffffffu, var, o);
    float rstd = rsqrtf(var * (1.f / 256.f) + 1e-5f);
    float* orow = out + (size_t)row * 257;
    #pragma unroll
    for (int i = 0; i < 8; i++) {
        int d = lane + i * 32;
        orow[d] = (v[i] - mu) * rstd * w[d] + b[d];
    }
    if (lane == 0) orow[256] = res[row];
}

// ---------------------------------------------------------------------------
// bf16 cp.async GEMM (r14-proven): BM=128 BN=64 BK=32, 3-stage cp.async,
// ldmatrix.x4 fragment loads, packed epilogue stores, __launch_bounds__(256,4).
// MODE 0: C[M,N] f32 store
// MODE 1: C[M,N] f32 accumulate (float2 when N even)
// MODE 2: dt path: edb = half2(exp(-sp), sp*u), exp(-sp) via sigmoid identity
// MODE 3: C f32 store + bf16x2 copy of cols<side_r into side
// MODE 4: bf16x2 store into side (ld side_ld), no f32
// ---------------------------------------------------------------------------
__device__ __forceinline__ void mma_bf16(float* c, const unsigned* a, const unsigned* b) {
    asm volatile(
        "mma.sync.aligned.m16n8k16.row.col.f32.bf16.bf16.f32 "
        "{%0,%1,%2,%3}, {%4,%5,%6,%7}, {%8,%9}, {%0,%1,%2,%3};"
        : "+f"(c[0]), "+f"(c[1]), "+f"(c[2]), "+f"(c[3])
        : "r"(a[0]), "r"(a[1]), "r"(a[2]), "r"(a[3]), "r"(b[0]), "r"(b[1]));
}

__device__ __forceinline__ void cpasync16(void* smem, const void* gmem) {
    unsigned saddr = (unsigned)__cvta_generic_to_shared(smem);
    asm volatile("cp.async.cg.shared.global [%0], [%1], 16;\n" :: "r"(saddr), "l"(gmem));
}

__device__ __forceinline__ void ldsm_x4(unsigned& r0, unsigned& r1,
                                        unsigned& r2, unsigned& r3, unsigned addr) {
    asm volatile("ldmatrix.sync.aligned.m8n8.x4.shared.b16 {%0,%1,%2,%3}, [%4];"
                 : "=r"(r0), "=r"(r1), "=r"(r2), "=r"(r3) : "r"(addr));
}

#define SWZ(row, c) (((((c) >> 2) ^ (((row) >> 1) & 3)) << 2) + ((c) & 3))

template <int MODE>
__global__ __launch_bounds__(256, 4)
void gemm_bf16_async(const __nv_bfloat16* __restrict__ A,
                     const __nv_bfloat16* __restrict__ W,
                     float* __restrict__ C, int M, int N, int Kpad,
                     const float* __restrict__ bias,
                     __nv_bfloat16* __restrict__ side, int side_ld, int side_r,
                     const __nv_bfloat16* __restrict__ ubf, int u_ld,
                     __half2* __restrict__ edb) {
    __shared__ unsigned As[GSTAGES][128 * 16];
    __shared__ unsigned Bs[GSTAGES][64 * 16];

    int tid  = threadIdx.x;
    int lane = tid & 31;
    int warp = tid >> 5;
    int wm = warp & 3, wn = warp >> 2;
    int g = lane >> 2, tg = lane & 3;
    int bm = blockIdx.y * 128;
    int bn = blockIdx.x * 64;
    int ntile = Kpad >> 5;

    int tq = lane >> 3, rl = lane & 7;
    unsigned as_base = (unsigned)__cvta_generic_to_shared(&As[0][0]);
    unsigned bs_base = (unsigned)__cvta_generic_to_shared(&Bs[0][0]);
    int rowA[2];
    rowA[0] = wm * 32 + 0  + (tq & 1) * 8 + rl;
    rowA[1] = wm * 32 + 16 + (tq & 1) * 8 + rl;
    int chA = tq >> 1;
    int colB[2];
    colB[0] = wn * 32 + 0  + (tq >> 1) * 8 + rl;
    colB[1] = wn * 32 + 16 + (tq >> 1) * 8 + rl;
    int chB = tq & 1;

    float acc[2][4][4];
    #pragma unroll
    for (int mt = 0; mt < 2; mt++)
        #pragma unroll
        for (int nt = 0; nt < 4; nt++)
            #pragma unroll
            for (int i = 0; i < 4; i++) acc[mt][nt][i] = 0.f;

    auto issue = [&](int buf, int t) {
        int k0 = t << 5;
        #pragma unroll
        for (int i = 0; i < 2; i++) {
            int idx = i * 256 + tid;
            int row = idx >> 2, ch = idx & 3;
            cpasync16(&As[buf][row * 16 + ((ch ^ ((row >> 1) & 3)) << 2)],
                      A + (size_t)(bm + row) * Kpad + k0 + ch * 8);
        }
        {
            int row = tid >> 2, ch = tid & 3;
            cpasync16(&Bs[buf][row * 16 + ((ch ^ ((row >> 1) & 3)) << 2)],
                      W + (size_t)(bn + row) * Kpad + k0 + ch * 8);
        }
        asm volatile("cp.async.commit_group;\n");
    };

    #pragma unroll
    for (int t = 0; t < GSTAGES - 1; t++) {
        if (t < ntile) issue(t, t);
        else asm volatile("cp.async.commit_group;\n");
    }

    for (int t = 0; t < ntile; t++) {
        asm volatile("cp.async.wait_group 1;\n");
        __syncthreads();
        int tn = t + GSTAGES - 1;
        if (tn < ntile) issue(tn % GSTAGES, tn);
        else asm volatile("cp.async.commit_group;\n");

        int buf = t % GSTAGES;
        unsigned abuf = as_base + (unsigned)(buf * 128 * 16 * 4);
        unsigned bbuf = bs_base + (unsigned)(buf * 64 * 16 * 4);
        #pragma unroll
        for (int ks = 0; ks < 2; ks++) {
            unsigned afr[2][4], bfr[4][2];
            #pragma unroll
            for (int mt = 0; mt < 2; mt++) {
                int r = rowA[mt];
                int ch = ks * 2 + chA;
                unsigned off = (unsigned)(r * 16 + ((ch ^ ((r >> 1) & 3)) << 2)) * 4u;
                ldsm_x4(afr[mt][0], afr[mt][1], afr[mt][2], afr[mt][3], abuf + off);
            }
            #pragma unroll
            for (int p = 0; p < 2; p++) {
                int cc = colB[p];
                int ch = ks * 2 + chB;
                unsigned off = (unsigned)(cc * 16 + ((ch ^ ((cc >> 1) & 3)) << 2)) * 4u;
                ldsm_x4(bfr[2 * p][0], bfr[2 * p][1],
                        bfr[2 * p + 1][0], bfr[2 * p + 1][1], bbuf + off);
            }
            #pragma unroll
            for (int mt = 0; mt < 2; mt++)
                #pragma unroll
                for (int nt = 0; nt < 4; nt++)
                    mma_bf16(acc[mt][nt], afr[mt], bfr[nt]);
        }
    }

    // epilogue — packed column-pair stores
    #pragma unroll
    for (int mt = 0; mt < 2; mt++) {
        int row0 = bm + wm * 32 + mt * 16 + g;
        #pragma unroll
        for (int nt = 0; nt < 4; nt++) {
            int col = bn + wn * 32 + nt * 8 + tg * 2;   // always even
            float* c = acc[mt][nt];
            #pragma unroll
            for (int rr = 0; rr < 2; rr++) {
                int ro = row0 + rr * 8;
                float v0 = c[rr * 2 + 0];
                float v1 = c[rr * 2 + 1];
                if (MODE == 0) {
                    if (col < N)     C[(size_t)ro * N + col]     = v0;
                    if (col + 1 < N) C[(size_t)ro * N + col + 1] = v1;
                }
                if (MODE == 1) {
                    if ((N & 1) == 0) {
                        if (col < N) {
                            float2* p = reinterpret_cast<float2*>(&C[(size_t)ro * N + col]);
                            float2 o = *p;
                            o.x += v0; o.y += v1;
                            *p = o;
                        }
                    } else {
                        if (col < N)     { size_t ix = (size_t)ro * N + col;     C[ix] += v0; }
                        if (col + 1 < N) { size_t ix = (size_t)ro * N + col + 1; C[ix] += v1; }
                    }
                }
                if (MODE == 2) {
                    if (col < N) {   // N even; col even -> col+1 < N too
                        float x0 = v0 + bias[col];
                        float x1 = v1 + bias[col + 1];
                        float q0 = __expf(-fabsf(x0));
                        float q1 = __expf(-fabsf(x1));
                        float sp0 = fmaxf(x0, 0.f) + log1pf(q0);
                        float sp1 = fmaxf(x1, 0.f) + log1pf(q1);
                        // exp(-softplus(x)) == (x>=0 ? q : 1) / (1+q)  (exact)
                        float e0 = (x0 >= 0.f ? q0 : 1.f) / (1.f + q0);
                        float e1 = (x1 >= 0.f ? q1 : 1.f) / (1.f + q1);
                        __nv_bfloat162 uu = *reinterpret_cast<const __nv_bfloat162*>(
                            &ubf[(size_t)ro * u_ld + col]);
                        float u0 = __bfloat162float(uu.x);
                        float u1 = __bfloat162float(uu.y);
                        __half2 p0 = __floats2half2_rn(e0, sp0 * u0);
                        __half2 p1 = __floats2half2_rn(e1, sp1 * u1);
                        uint2 pk;
                        pk.x = *reinterpret_cast<unsigned*>(&p0);
                        pk.y = *reinterpret_cast<unsigned*>(&p1);
                        *reinterpret_cast<uint2*>(&edb[(size_t)ro * N + col]) = pk;
                    }
                }
                if (MODE == 3) {
                    if (col < N)     C[(size_t)ro * N + col]     = v0;
                    if (col + 1 < N) C[(size_t)ro * N + col + 1] = v1;
                    if (col < side_r) {
                        *reinterpret_cast<__nv_bfloat162*>(
                            &side[(size_t)ro * side_ld + col]) =
                            __floats2bfloat162_rn(v0, v1);
                    }
                }
                if (MODE == 4) {
                    if (col < N) {   // N even
                        *reinterpret_cast<__nv_bfloat162*>(
                            &side[(size_t)ro * side_ld + col]) =
                            __floats2bfloat162_rn(v0, v1);
                    }
                }
            }
        }
    }
}

// ---------------------------------------------------------------------------
// Fused depthwise causal conv1d (K=4) + SiLU + z-gate precompute (r14-proven).
// Channel-PAIR: bf16x2 smem reads, bf16x2 x_bf store, 8B uz store.
// ---------------------------------------------------------------------------
__global__ void conv_fused_kernel(const __nv_bfloat16* __restrict__ xz, int ld_xz,
                                  const float* __restrict__ cw,
                                  const float* __restrict__ cb,
                                  const float* __restrict__ Dp,
                                  __nv_bfloat16* __restrict__ x_bf, int ld_xbf,
                                  __half2* __restrict__ uz,
                                  int di) {
    __shared__ __nv_bfloat16 sx[CTOK + 3][128];
    __shared__ float scw[4][128], scb[128], sD[128];
    int tid = threadIdx.x;
    int c0 = blockIdx.x * 128;
    int t0 = blockIdx.y * CTOK;
    int l0 = t0 & (SEQ - 1);

    if (tid < 128) {
        int ch = c0 + tid;
        bool ok = ch < di;
        scb[tid] = ok ? cb[ch] : 0.f;
        sD[tid]  = ok ? Dp[ch] : 0.f;
        #pragma unroll
        for (int k = 0; k < 4; k++) scw[k][tid] = ok ? cw[ch * 4 + k] : 0.f;
    }
    for (int idx = tid; idx < (CTOK + 3) * 128; idx += 256) {
        int row = idx >> 7, chl = idx & 127;
        int ch = c0 + chl;
        int token = t0 - 3 + row;
        __nv_bfloat16 v = __float2bfloat16(0.f);
        if (ch < di && (row >= 3 || l0 > 0))
            v = xz[(size_t)token * ld_xz + ch];
        sx[row][chl] = v;
    }
    __syncthreads();

    int cp  = tid & 63;          // channel pair index
    int th  = tid >> 6;          // token group 0..3
    int chl = cp * 2;
    int c   = c0 + chl;
    if (c >= di) return;         // di even -> c+1 < di whenever c < di
    float w0a = scw[0][chl],     w1a = scw[1][chl],     w2a = scw[2][chl],     w3a = scw[3][chl];
    float w0b = scw[0][chl + 1], w1b = scw[1][chl + 1], w2b = scw[2][chl + 1], w3b = scw[3][chl + 1];
    float bba = scb[chl], bbb = scb[chl + 1];
    float Da  = sD[chl],  Db  = sD[chl + 1];

    for (int tt = 0; tt < CTOK / 4; tt++) {
        int tl = th * (CTOK / 4) + tt;
        size_t token = (size_t)t0 + tl;
        float2 x0 = __bfloat1622float2(*reinterpret_cast<const __nv_bfloat162*>(&sx[tl][chl]));
        float2 x1 = __bfloat1622float2(*reinterpret_cast<const __nv_bfloat162*>(&sx[tl + 1][chl]));
        float2 x2 = __bfloat1622float2(*reinterpret_cast<const __nv_bfloat162*>(&sx[tl + 2][chl]));
        float2 x3 = __bfloat1622float2(*reinterpret_cast<const __nv_bfloat162*>(&sx[tl + 3][chl]));
        float acc0 = bba + w0a * x0.x + w1a * x1.x + w2a * x2.x + w3a * x3.x;
        float acc1 = bbb + w0b * x0.y + w1b * x1.y + w2b * x2.y + w3b * x3.y;
        float u0 = acc0 / (1.f + __expf(-acc0));
        float u1 = acc1 / (1.f + __expf(-acc1));
        *reinterpret_cast<__nv_bfloat162*>(&x_bf[token * ld_xbf + c]) =
            __floats2bfloat162_rn(u0, u1);
        float2 zz = __bfloat1622float2(*reinterpret_cast<const __nv_bfloat162*>(
            &xz[token * ld_xz + di + c]));
        float zg0 = zz.x / (1.f + __expf(-zz.x));
        float zg1 = zz.y / (1.f + __expf(-zz.y));
        __half2 p0 = __floats2half2_rn(zg0, u0 * Da * zg0);
        __half2 p1 = __floats2half2_rn(zg1, u1 * Db * zg1);
        uint2 pk;
        pk.x = *reinterpret_cast<unsigned*>(&p0);
        pk.y = *reinterpret_cast<unsigned*>(&p1);
        *reinterpret_cast<uint2*>(&uz[token * di + c]) = pk;
    }
}

// ---------------------------------------------------------------------------
// Chunked parallel selective scan. B/C staging stride-16/32 (16B-aligned) so
// broadcast reads collapse into LDS.128 (4:1 issue reduction in hot loop).
// Write phase stays conflict-free (banks 0..31 covered exactly once).
// ---------------------------------------------------------------------------
__global__ void scan_pass1(const __half2* __restrict__ edb,
                           const float* __restrict__ xdbl, int ld_xd, int r,
                           const float* __restrict__ A_log,
                           float* __restrict__ P, float* __restrict__ S,
                           int di) {
    __shared__ float4 sB4[CHUNK][4];          // [t][4] = 16 floats per token
    __shared__ float sA[128][17];
    float* sB = reinterpret_cast<float*>(sB4);
    int tid = threadIdx.x;
    int c0 = blockIdx.x * 128, chunk = blockIdx.y, b = blockIdx.z;
    size_t tok0 = (size_t)b * SEQ + (size_t)chunk * CHUNK;
    for (int i = tid; i < CHUNK * 16; i += 128) {
        int tt = i >> 4, s = i & 15;
        sB[tt * 16 + s] = xdbl[(tok0 + tt) * ld_xd + r + s];
    }
    for (int i = tid; i < 128 * 16; i += 128) {
        int cc = i >> 4, s = i & 15;
        int ch = c0 + cc;
        sA[cc][s] = (ch < di) ? A_log[(size_t)ch * 16 + s] : 0.f;
    }
    __syncthreads();
    int c = c0 + tid;
    if (c >= di) return;

    bool fast = true;
    float a[16];
    #pragma unroll
    for (int s = 0; s < 16; s++) {
        a[s] = -__expf(sA[tid][s]);
        fast = fast && (fabsf(a[s] + (float)(s + 1)) <= 1e-5f * (float)(s + 1));
    }
    float st[16];
    #pragma unroll
    for (int s = 0; s < 16; s++) st[s] = 0.f;
    size_t obase = ((size_t)(b * NCH + chunk) * 16) * di + c;

    if (fast) {
        float prodE = 1.f;
        for (int t = 0; t < CHUNK; t++) {
            size_t tok = tok0 + t;
            float2 ed = __half22float2(edb[tok * di + c]);
            float e = ed.x, db = ed.y;
            prodE *= e;
            float4 q0 = sB4[t][0], q1 = sB4[t][1], q2 = sB4[t][2], q3 = sB4[t][3];
            float bv[16] = {q0.x, q0.y, q0.z, q0.w, q1.x, q1.y, q1.z, q1.w,
                            q2.x, q2.y, q2.z, q2.w, q3.x, q3.y, q3.z, q3.w};
            float ep = 1.f;
            #pragma unroll
            for (int s = 0; s < 16; s++) {
                ep *= e;
                st[s] = ep * st[s] + db * bv[s];
            }
        }
        float pp = 1.f;
        #pragma unroll
        for (int s = 0; s < 16; s++) {
            pp *= prodE;
            P[obase + (size_t)s * di] = pp;
            S[obase + (size_t)s * di] = st[s];
        }
    } else {
        float Pl[16];
        #pragma unroll
        for (int s = 0; s < 16; s++) Pl[s] = 1.f;
        for (int t = 0; t < CHUNK; t++) {
            size_t tok = tok0 + t;
            float2 ed = __half22float2(edb[tok * di + c]);
            float e = ed.x, db = ed.y;
            float4 q0 = sB4[t][0], q1 = sB4[t][1], q2 = sB4[t][2], q3 = sB4[t][3];
            float bv[16] = {q0.x, q0.y, q0.z, q0.w, q1.x, q1.y, q1.z, q1.w,
                            q2.x, q2.y, q2.z, q2.w, q3.x, q3.y, q3.z, q3.w};
            #pragma unroll
            for (int s = 0; s < 16; s++) {
                float dA = __powf(e, -a[s]);
                st[s] = dA * st[s] + db * bv[s];
                Pl[s] *= dA;
            }
        }
        #pragma unroll
        for (int s = 0; s < 16; s++) {
            P[obase + (size_t)s * di] = Pl[s];
            S[obase + (size_t)s * di] = st[s];
        }
    }
}

// ILP-batched serial chunk combine (r16-proven).
__global__ void scan_pass2(float* __restrict__ P, float* __restrict__ S, int di) {
    int per_b = 16 * di;
    int gi = blockIdx.x * blockDim.x + threadIdx.x;
    if (gi >= BATCH * per_b) return;
    int b = gi / per_b;
    int sc = gi - b * per_b;
    size_t base = (size_t)b * NCH * per_b + sc;
    float st = 0.f;
    #pragma unroll
    for (int cg = 0; cg < NCH; cg += 8) {
        float p[8], sv[8];
        #pragma unroll
        for (int j = 0; j < 8; j++) {
            size_t idx = base + (size_t)(cg + j) * per_b;
            p[j]  = P[idx];
            sv[j] = S[idx];
        }
        #pragma unroll
        for (int j = 0; j < 8; j++) {
            size_t idx = base + (size_t)(cg + j) * per_b;
            S[idx] = st;            // init state entering chunk cg+j
            st = p[j] * st + sv[j];
        }
    }
}

__global__ void scan_pass3(const __half2* __restrict__ edb,
                           const float* __restrict__ xdbl, int ld_xd, int r,
                           const float* __restrict__ A_log,
                           const float* __restrict__ S,
                           const __half2* __restrict__ uz,
                           __nv_bfloat16* __restrict__ yg, int ld_yg,
                           int di) {
    __shared__ float4 sBC4[CHUNK][8];         // [t][8] = 32 floats (B then C)
    __shared__ float sA[128][17];
    float* sBC = reinterpret_cast<float*>(sBC4);
    int tid = threadIdx.x;
    int c0 = blockIdx.x * 128, chunk = blockIdx.y, b = blockIdx.z;
    size_t tok0 = (size_t)b * SEQ + (size_t)chunk * CHUNK;
    for (int i = tid; i < CHUNK * 32; i += 128) {
        int tt = i >> 5, s = i & 31;
        sBC[tt * 32 + s] = xdbl[(tok0 + tt) * ld_xd + r + s];
    }
    for (int i = tid; i < 128 * 16; i += 128) {
        int cc = i >> 4, s = i & 15;
        int ch = c0 + cc;
        sA[cc][s] = (ch < di) ? A_log[(size_t)ch * 16 + s] : 0.f;
    }
    __syncthreads();
    int c = c0 + tid;
    if (c >= di) return;

    bool fast = true;
    float a[16];
    #pragma unroll
    for (int s = 0; s < 16; s++) {
        a[s] = -__expf(sA[tid][s]);
        fast = fast && (fabsf(a[s] + (float)(s + 1)) <= 1e-5f * (float)(s + 1));
    }
    float st[16];
    size_t sbase = ((size_t)(b * NCH + chunk) * 16) * di + c;
    #pragma unroll
    for (int s = 0; s < 16; s++) st[s] = S[sbase + (size_t)s * di];

    if (fast) {
        for (int t = 0; t < CHUNK; t++) {
            size_t tok = tok0 + t;
            float2 ed = __half22float2(edb[tok * di + c]);
            float e = ed.x, db = ed.y;
            float4 q0 = sBC4[t][0], q1 = sBC4[t][1], q2 = sBC4[t][2], q3 = sBC4[t][3];
            float4 r0 = sBC4[t][4], r1 = sBC4[t][5], r2 = sBC4[t][6], r3 = sBC4[t][7];
            float bv[16] = {q0.x, q0.y, q0.z, q0.w, q1.x, q1.y, q1.z, q1.w,
                            q2.x, q2.y, q2.z, q2.w, q3.x, q3.y, q3.z, q3.w};
            float cv[16] = {r0.x, r0.y, r0.z, r0.w, r1.x, r1.y, r1.z, r1.w,
                            r2.x, r2.y, r2.z, r2.w, r3.x, r3.y, r3.z, r3.w};
            float y = 0.f, ep = 1.f;
            #pragma unroll
            for (int s = 0; s < 16; s++) {
                ep *= e;
                st[s] = ep * st[s] + db * bv[s];
                y += st[s] * cv[s];
            }
            float2 g = __half22float2(uz[tok * di + c]);
            yg[tok * ld_yg + c] = __float2bfloat16(y * g.x + g.y);
        }
    } else {
        for (int t = 0; t < CHUNK; t++) {
            size_t tok = tok0 + t;
            float2 ed = __half22float2(edb[tok * di + c]);
            float e = ed.x, db = ed.y;
            float4 q0 = sBC4[t][0], q1 = sBC4[t][1], q2 = sBC4[t][2], q3 = sBC4[t][3];
            float4 r0 = sBC4[t][4], r1 = sBC4[t][5], r2 = sBC4[t][6], r3 = sBC4[t][7];
            float bv[16] = {q0.x, q0.y, q0.z, q0.w, q1.x, q1.y, q1.z, q1.w,
                            q2.x, q2.y, q2.z, q2.w, q3.x, q3.y, q3.z, q3.w};
            float cv[16] = {r0.x, r0.y, r0.z, r0.w, r1.x, r1.y, r1.z, r1.w,
                            r2.x, r2.y, r2.z, r2.w, r3.x, r3.y, r3.z, r3.w};
            float y = 0.f;
            #pragma unroll
            for (int s = 0; s < 16; s++) {
                float dA = __powf(e, -a[s]);
                st[s] = dA * st[s] + db * bv[s];
                y += st[s] * cv[s];
            }
            float2 g = __half22float2(uz[tok * di + c]);
            yg[tok * ld_yg + c] = __float2bfloat16(y * g.x + g.y);
        }
    }
}

// ---------------------------------------------------------------------------
// Mean pool + classifier
// ---------------------------------------------------------------------------
__global__ void pool_kernel(const float* __restrict__ hn, float* __restrict__ pool) {
    int b = blockIdx.x, dd = blockIdx.y;
    float s = 0.f;
    for (int l = threadIdx.x; l < SEQ; l += 128)
        s += hn[((size_t)b * SEQ + l) * 257 + dd];
    __shared__ float red[128];
    red[threadIdx.x] = s;
    __syncthreads();
    for (int o = 64; o; o >>= 1) {
        if (threadIdx.x < o) red[threadIdx.x] += red[threadIdx.x + o];
        __syncthreads();
    }
    if (threadIdx.x == 0) pool[b * 257 + dd] = red[0] * (1.f / (float)SEQ);
}

__global__ void cls_kernel(const float* __restrict__ pool,
                           const float* __restrict__ w,
                           const float* __restrict__ bias,
                           float* __restrict__ out) {
    int i = threadIdx.x;
    if (i >= BATCH * 16) return;
    int b = i >> 4, n = i & 15;
    float acc = bias[n];
    for (int dd = 0; dd < 257; dd++) acc += pool[b * 257 + dd] * w[n * 257 + dd];
    out[b * 16 + n] = acc;
}

// ---------------------------------------------------------------------------
// Host orchestration
// ---------------------------------------------------------------------------
static inline int align32(int x) { return (x + 31) & ~31; }

static inline void launch_gemm(const __nv_bfloat16* A, const __nv_bfloat16* W,
                               float* C, int M, int N, int Kpad, int mode,
                               const float* bias = nullptr,
                               __nv_bfloat16* side = nullptr, int side_ld = 0,
                               int side_r = 0,
                               const __nv_bfloat16* ubf = nullptr, int u_ld = 0,
                               __half2* edb = nullptr) {
    dim3 grid((N + 63) / 64, M / 128);
    switch (mode) {
    case 0: gemm_bf16_async<0><<<grid, 256>>>(A, W, C, M, N, Kpad, bias, side, side_ld, side_r, ubf, u_ld, edb); break;
    case 1: gemm_bf16_async<1><<<grid, 256>>>(A, W, C, M, N, Kpad, bias, side, side_ld, side_r, ubf, u_ld, edb); break;
    case 2: gemm_bf16_async<2><<<grid, 256>>>(A, W, C, M, N, Kpad, bias, side, side_ld, side_r, ubf, u_ld, edb); break;
    case 3: gemm_bf16_async<3><<<grid, 256>>>(A, W, C, M, N, Kpad, bias, side, side_ld, side_r, ubf, u_ld, edb); break;
    default: gemm_bf16_async<4><<<grid, 256>>>(A, W, C, M, N, Kpad, bias, side, side_ld, side_r, ubf, u_ld, edb); break;
    }
}

static void mamba_block(float* hbuf, int d, int di, int r,
                        const float* ln_w, const float* ln_b,
                        const float* conv_w, const float* conv_b,
                        const float* dt_b, const float* A_log, const float* Dp,
                        const __nv_bfloat16* w_in, const __nv_bfloat16* w_xp,
                        const __nv_bfloat16* w_dt, const __nv_bfloat16* w_out,
                        __nv_bfloat16* hn_bf, __nv_bfloat16* xz_bf,
                        __nv_bfloat16* x_bf, float* xdbl, __nv_bfloat16* xdbl_bf,
                        __half2* edb, __half2* uz,
                        __nv_bfloat16* yg_bf, float* Pbuf, float* Sbuf) {
    int xdw = r + 2 * DSTATE;
    int dpad = align32(d), dipad = align32(di);

    ln_bf16_kernel<<<NT / 8, 256>>>(hbuf, hn_bf, ln_w, ln_b, d, dpad);
    // in-proj -> xz bf16 only
    launch_gemm(hn_bf, w_in, nullptr, NT, 2 * di, dpad, 4,
                nullptr, xz_bf, 1056, 0);
    // fused conv + silu + z-gate precompute
    conv_fused_kernel<<<dim3((di + 127) / 128, NT / CTOK), 256>>>(
        xz_bf, 1056, conv_w, conv_b, Dp, x_bf, dipad, uz, di);
    // x-proj -> xdbl f32 + bf16 side (dt_r part)
    launch_gemm(x_bf, w_xp, xdbl, NT, xdw, dipad, 3,
                nullptr, xdbl_bf, 32, r);
    // dt path: edb = half2(exp(-softplus), dt*u)
    launch_gemm(xdbl_bf, w_dt, nullptr, NT, di, 32, 2,
                dt_b, nullptr, 0, 0, x_bf, dipad, edb);
    // chunked parallel scan
    dim3 sg((di + 127) / 128, NCH, BATCH);
    scan_pass1<<<sg, 128>>>(edb, xdbl, xdw, r, A_log, Pbuf, Sbuf, di);
    scan_pass2<<<(BATCH * 16 * di + 255) / 256, 256>>>(Pbuf, Sbuf, di);
    scan_pass3<<<sg, 128>>>(edb, xdbl, xdw, r, A_log, Sbuf,
                            uz, yg_bf, dipad, di);
    // out-proj with fused residual add
    launch_gemm(yg_bf, w_out, hbuf, NT, d, dipad, 1);
}

extern "C" void kernel_launch(void* const* d_in, const int* in_sizes, int n_in,
                              void* d_out, int out_size) {
    const int*   x         = (const int*)  d_in[0];
    const float* emb       = (const float*)d_in[1];
    const float* blk_ln_w  = (const float*)d_in[2];
    const float* blk_ln_b  = (const float*)d_in[3];
    const float* blk_in_w  = (const float*)d_in[4];
    const float* blk_cv_w  = (const float*)d_in[5];
    const float* blk_cv_b  = (const float*)d_in[6];
    const float* blk_xp_w  = (const float*)d_in[7];
    const float* blk_dt_w  = (const float*)d_in[8];
    const float* blk_dt_b  = (const float*)d_in[9];
    const float* blk_A_log = (const float*)d_in[10];
    const float* blk_D     = (const float*)d_in[11];
    const float* blk_out_w = (const float*)d_in[12];
    const float* norm_w    = (const float*)d_in[13];
    const float* norm_b    = (const float*)d_in[14];
    const float* cmb_ln_w  = (const float*)d_in[15];
    const float* cmb_ln_b  = (const float*)d_in[16];
    const float* cmb_in_w  = (const float*)d_in[17];
    const float* cmb_cv_w  = (const float*)d_in[18];
    const float* cmb_cv_b  = (const float*)d_in[19];
    const float* cmb_xp_w  = (const float*)d_in[20];
    const float* cmb_dt_w  = (const float*)d_in[21];
    const float* cmb_dt_b  = (const float*)d_in[22];
    const float* cmb_A_log = (const float*)d_in[23];
    const float* cmb_D     = (const float*)d_in[24];
    const float* cmb_out_w = (const float*)d_in[25];
    const float* fin_w     = (const float*)d_in[26];
    const float* fin_b     = (const float*)d_in[27];
    const float* cls_w     = (const float*)d_in[28];
    const float* cls_b     = (const float*)d_in[29];
    float* out = (float*)d_out;

    float *p_h, *p_hc, *p_hn, *p_xdbl, *p_res, *p_pool, *p_P, *p_S;
    __nv_bfloat16 *p_hn_bf, *p_xz_bf, *p_x_bf, *p_xdbl_bf, *p_yg_bf, *p_wbf;
    __half2 *p_edb, *p_uz;
    cudaGetSymbolAddress((void**)&p_h,       g_h);
    cudaGetSymbolAddress((void**)&p_hc,      g_hc);
    cudaGetSymbolAddress((void**)&p_hn,      g_hn);
    cudaGetSymbolAddress((void**)&p_hn_bf,   g_hn_bf);
    cudaGetSymbolAddress((void**)&p_xz_bf,   g_xz_bf);
    cudaGetSymbolAddress((void**)&p_x_bf,    g_x_bf);
    cudaGetSymbolAddress((void**)&p_xdbl,    g_xdbl);
    cudaGetSymbolAddress((void**)&p_xdbl_bf, g_xdbl_bf);
    cudaGetSymbolAddress((void**)&p_edb,     g_edb);
    cudaGetSymbolAddress((void**)&p_uz,      g_uz);
    cudaGetSymbolAddress((void**)&p_yg_bf,   g_yg_bf);
    cudaGetSymbolAddress((void**)&p_res,     g_res);
    cudaGetSymbolAddress((void**)&p_pool,    g_pool);
    cudaGetSymbolAddress((void**)&p_P,       g_P);
    cudaGetSymbolAddress((void**)&p_S,       g_S);
    cudaGetSymbolAddress((void**)&p_wbf,     g_wbf);

    // -------- weight table (deterministic offsets) --------
    WTab tab;
    long long off = 0;
    int wi = 0;
    long long w_in_off[5], w_xp_off[5], w_dt_off[5], w_out_off[5];
    auto add = [&](const float* src, int N, int K) -> long long {
        int Kp = align32(K);
        int Np = (N + 63) & ~63;
        long long o = off;
        tab.w[wi].src = src; tab.w[wi].off = o;
        tab.w[wi].N = N; tab.w[wi].K = K; tab.w[wi].Kpad = Kp;
        tab.w[wi].total = Np * Kp;
        wi++;
        off += (long long)Np * Kp;
        return o;
    };
    for (int i = 0; i < 4; i++) {
        w_in_off[i]  = add(blk_in_w  + (size_t)i * 1024 * 256, 1024, 256);
        w_xp_off[i]  = add(blk_xp_w  + (size_t)i * 48 * 512,   48,  512);
        w_dt_off[i]  = add(blk_dt_w  + (size_t)i * 512 * 16,   512, 16);
        w_out_off[i] = add(blk_out_w + (size_t)i * 256 * 512,  256, 512);
    }
    w_in_off[4]  = add(cmb_in_w,  1028, 257);
    w_xp_off[4]  = add(cmb_xp_w,  49,  514);
    w_dt_off[4]  = add(cmb_dt_w,  514, 17);
    w_out_off[4] = add(cmb_out_w, 257, 514);

    wconv_kernel<<<dim3(1224, 20), 256>>>(tab, p_wbf);
    embed_kernel<<<NT, 64>>>(x, emb, p_h, p_res);

    for (int i = 0; i < 4; i++) {
        mamba_block(p_h, 256, 512, 16,
                    blk_ln_w + (size_t)i * 256, blk_ln_b + (size_t)i * 256,
                    blk_cv_w + (size_t)i * 512 * 4, blk_cv_b + (size_t)i * 512,
                    blk_dt_b + (size_t)i * 512,
                    blk_A_log + (size_t)i * 512 * 16, blk_D + (size_t)i * 512,
                    p_wbf + w_in_off[i], p_wbf + w_xp_off[i],
                    p_wbf + w_dt_off[i], p_wbf + w_out_off[i],
                    p_hn_bf, p_xz_bf, p_x_bf, p_xdbl, p_xdbl_bf,
                    p_edb, p_uz, p_yg_bf, p_P, p_S);
    }

    ln_concat_kernel<<<NT / 8, 256>>>(p_h, p_hc, norm_w, norm_b, p_res);

    mamba_block(p_hc, 257, 514, 17,
                cmb_ln_w, cmb_ln_b, cmb_cv_w, cmb_cv_b, cmb_dt_b,
                cmb_A_log, cmb_D,
                p_wbf + w_in_off[4], p_wbf + w_xp_off[4],
                p_wbf + w_dt_off[4], p_wbf + w_out_off[4],
                p_hn_bf, p_xz_bf, p_x_bf, p_xdbl, p_xdbl_bf,
                p_edb, p_uz, p_yg_bf, p_P, p_S);

    ln_kernel<<<NT / 8, 256>>>(p_hc, p_hn, fin_w, fin_b, 257, NT);
    pool_kernel<<<dim3(BATCH, 257), 128>>>(p_hn, p_pool);
    cls_kernel<<<1, 128>>>(p_pool, cls_w, cls_b, out);
}